// round 1
// baseline (speedup 1.0000x reference)
#include <cuda_runtime.h>
#include <math.h>

// Problem constants
#define SQ   2048
#define H    4096
#define NQ   32
#define NKV  8
#define HD   128
#define II   14336
#define QKVN (NQ*HD + 2*NKV*HD)   // 6144
#define GUN  (2*II)               // 28672

// ---------------------------------------------------------------------------
// Scratch (device globals; no allocation anywhere)
// ---------------------------------------------------------------------------
__device__ float g_xn  [SQ * H];            // rmsnorm1 output
__device__ float g_qkv [SQ * QKVN];         // qkv projection (rope applied in place)
__device__ float g_attn[SQ * H];            // attention output (pre w_o)
__device__ float g_xn2 [SQ * H];            // rmsnorm2 output
__device__ float g_gu  [SQ * GUN];          // gate/up projection
__device__ float g_hh  [SQ * II];           // silu(gate)*up
__device__ float g_res [SQ * H];            // residual fallback if out_size small

// ---------------------------------------------------------------------------
// RMSNorm: one block per row, 256 threads
// ---------------------------------------------------------------------------
__global__ void rmsnorm_kernel(const float* __restrict__ x,
                               const float* __restrict__ w,
                               float* __restrict__ y) {
    int row = blockIdx.x;
    const float4* xr = (const float4*)(x + (size_t)row * H);
    float4*       yr = (float4*)(y + (size_t)row * H);
    const float4* wv = (const float4*)w;

    float s = 0.f;
    for (int i = threadIdx.x; i < H / 4; i += 256) {
        float4 v = xr[i];
        s += v.x * v.x + v.y * v.y + v.z * v.z + v.w * v.w;
    }
    __shared__ float red[256];
    red[threadIdx.x] = s;
    __syncthreads();
    for (int off = 128; off; off >>= 1) {
        if (threadIdx.x < off) red[threadIdx.x] += red[threadIdx.x + off];
        __syncthreads();
    }
    float inv = rsqrtf(red[0] / (float)H + 1e-5f);

    for (int i = threadIdx.x; i < H / 4; i += 256) {
        float4 v = xr[i];
        float4 g = wv[i];
        float4 o;
        o.x = v.x * inv * g.x; o.y = v.y * inv * g.y;
        o.z = v.z * inv * g.z; o.w = v.w * inv * g.w;
        yr[i] = o;
    }
}

// ---------------------------------------------------------------------------
// RoPE (in-place on q and k regions of g_qkv)
// grid: (SQ, NQ+NKV), 64 threads (one per rotary pair index)
// ---------------------------------------------------------------------------
__global__ void rope_kernel(const int* __restrict__ pos, float* __restrict__ qkv) {
    int s  = blockIdx.x;
    int hh = blockIdx.y;           // 0..31 = q heads, 32..39 = k heads
    int i  = threadIdx.x;          // 0..63
    int base = (hh < NQ) ? hh * HD : NQ * HD + (hh - NQ) * HD;
    float* p = qkv + (size_t)s * QKVN + base;

    float fpos = (float)pos[s];
    float invf = powf(10000.0f, -(float)i / 64.0f);
    float ang  = fpos * invf;
    float sn, cs;
    sincosf(ang, &sn, &cs);
    float x1 = p[i], x2 = p[i + 64];
    p[i]      = x1 * cs - x2 * sn;
    p[i + 64] = x2 * cs + x1 * sn;
}

// ---------------------------------------------------------------------------
// SGEMM: C[M,N] = A[M,K] @ B[K,N]  (+ optional residual R[M,N])
// BM=BN=128, BK=8, 256 threads, 8x8 per-thread microtile. All dims are
// multiples of the tile sizes for this problem, so no bounds checks.
// ---------------------------------------------------------------------------
template <int ADD_RESID>
__global__ void __launch_bounds__(256)
sgemm_kernel(int M, int N, int K,
             const float* __restrict__ A,
             const float* __restrict__ B,
             float* __restrict__ C,
             const float* __restrict__ R) {
    __shared__ float As[8][128];
    __shared__ float Bs[8][128];

    int tid  = threadIdx.x;
    int tx   = tid & 15;       // 0..15  -> N microtile
    int ty   = tid >> 4;       // 0..15  -> M microtile
    int arow = tid >> 1;       // 0..127
    int acol = (tid & 1) * 4;  // 0 or 4
    int brow = tid >> 5;       // 0..7
    int bcol = (tid & 31) * 4; // 0..124

    const float* Ab = A + (size_t)blockIdx.y * 128 * K;
    const float* Bb = B + (size_t)blockIdx.x * 128;

    float acc[8][8];
#pragma unroll
    for (int i = 0; i < 8; i++)
#pragma unroll
        for (int j = 0; j < 8; j++) acc[i][j] = 0.f;

    for (int k0 = 0; k0 < K; k0 += 8) {
        float4 a = *(const float4*)&Ab[(size_t)arow * K + k0 + acol];
        As[acol + 0][arow] = a.x;
        As[acol + 1][arow] = a.y;
        As[acol + 2][arow] = a.z;
        As[acol + 3][arow] = a.w;
        float4 b = *(const float4*)&Bb[(size_t)(k0 + brow) * N + bcol];
        *(float4*)&Bs[brow][bcol] = b;
        __syncthreads();

#pragma unroll
        for (int k = 0; k < 8; k++) {
            float ra[8], rb[8];
            *(float4*)&ra[0] = *(float4*)&As[k][ty * 8];
            *(float4*)&ra[4] = *(float4*)&As[k][ty * 8 + 4];
            *(float4*)&rb[0] = *(float4*)&Bs[k][tx * 8];
            *(float4*)&rb[4] = *(float4*)&Bs[k][tx * 8 + 4];
#pragma unroll
            for (int i = 0; i < 8; i++)
#pragma unroll
                for (int j = 0; j < 8; j++)
                    acc[i][j] += ra[i] * rb[j];
        }
        __syncthreads();
    }

#pragma unroll
    for (int i = 0; i < 8; i++) {
        size_t r = (size_t)blockIdx.y * 128 + ty * 8 + i;
#pragma unroll
        for (int j = 0; j < 8; j += 4) {
            size_t c = (size_t)blockIdx.x * 128 + tx * 8 + j;
            float4 v;
            v.x = acc[i][j + 0]; v.y = acc[i][j + 1];
            v.z = acc[i][j + 2]; v.w = acc[i][j + 3];
            if (ADD_RESID) {
                float4 rr = *(const float4*)&R[r * N + c];
                v.x += rr.x; v.y += rr.y; v.z += rr.z; v.w += rr.w;
            }
            *(float4*)&C[r * N + c] = v;
        }
    }
}

// ---------------------------------------------------------------------------
// Flash attention (causal, GQA G=4), fp32.
// Block = (q-tile of 64 rows, q-head). 256 threads.
// Per-thread: 4x4 score microtile (16x16 thread grid), 4x8 output microtile.
// ---------------------------------------------------------------------------
#define FA_QS   (64 * 128)
#define FA_KS   (64 * 132)
#define FA_VS   (64 * 128)
#define FA_PS   (64 * 65)
#define FA_SMEM ((FA_QS + FA_KS + FA_VS + FA_PS) * 4)

__global__ void __launch_bounds__(256)
flash_kernel(const float* __restrict__ qkv, float* __restrict__ attn) {
    extern __shared__ float sm[];
    float* Qs = sm;                 // [64][128]
    float* Ks = Qs + FA_QS;         // [64][132] (pad for banks)
    float* Vs = Ks + FA_KS;         // [64][128]
    float* Ps = Vs + FA_VS;         // [64][65]

    const int qb  = blockIdx.x;     // 0..31
    const int h   = blockIdx.y;     // 0..31
    const int kh  = h >> 2;         // GQA: kv head
    const int tid = threadIdx.x;
    const int tc  = tid & 15;
    const int tr  = tid >> 4;
    const float scale = 0.08838834764831845f; // 1/sqrt(128)

    // Load Q tile (pre-scaled)
    for (int i = tid; i < 64 * 32; i += 256) {
        int r  = i >> 5;
        int c4 = (i & 31) << 2;
        float4 v = *(const float4*)&qkv[(size_t)(qb * 64 + r) * QKVN + h * HD + c4];
        v.x *= scale; v.y *= scale; v.z *= scale; v.w *= scale;
        *(float4*)&Qs[r * 128 + c4] = v;
    }

    float o[4][8];
    float m[4], l[4];
#pragma unroll
    for (int i = 0; i < 4; i++) {
        m[i] = -1e30f; l[i] = 0.f;
#pragma unroll
        for (int j = 0; j < 8; j++) o[i][j] = 0.f;
    }

    for (int jt = 0; jt <= qb; jt++) {
        __syncthreads();
        // Load K, V tiles
        for (int i = tid; i < 64 * 32; i += 256) {
            int r  = i >> 5;
            int c4 = (i & 31) << 2;
            size_t rowoff = (size_t)(jt * 64 + r) * QKVN;
            float4 kv = *(const float4*)&qkv[rowoff + NQ * HD + kh * HD + c4];
            *(float4*)&Ks[r * 132 + c4] = kv;
            float4 vv = *(const float4*)&qkv[rowoff + (NQ + NKV) * HD + kh * HD + c4];
            *(float4*)&Vs[r * 128 + c4] = vv;
        }
        __syncthreads();

        // S = Q K^T (4x4 per thread)
        float s[4][4];
#pragma unroll
        for (int i = 0; i < 4; i++)
#pragma unroll
            for (int j = 0; j < 4; j++) s[i][j] = 0.f;

        for (int d = 0; d < 128; d += 4) {
            float4 qv[4], kv[4];
#pragma unroll
            for (int i = 0; i < 4; i++)
                qv[i] = *(const float4*)&Qs[(tr * 4 + i) * 128 + d];
#pragma unroll
            for (int j = 0; j < 4; j++)
                kv[j] = *(const float4*)&Ks[(tc * 4 + j) * 132 + d];
#pragma unroll
            for (int i = 0; i < 4; i++)
#pragma unroll
                for (int j = 0; j < 4; j++)
                    s[i][j] += qv[i].x * kv[j].x + qv[i].y * kv[j].y +
                               qv[i].z * kv[j].z + qv[i].w * kv[j].w;
        }

        // Causal mask on the diagonal tile
        if (jt == qb) {
#pragma unroll
            for (int i = 0; i < 4; i++) {
                int rl = tr * 4 + i;
#pragma unroll
                for (int j = 0; j < 4; j++) {
                    int cl = tc * 4 + j;
                    if (cl > rl) s[i][j] = -1e30f;
                }
            }
        }

        // Online softmax update (row groups of 16 lanes are lane-aligned)
#pragma unroll
        for (int i = 0; i < 4; i++) {
            float tmax = fmaxf(fmaxf(s[i][0], s[i][1]), fmaxf(s[i][2], s[i][3]));
#pragma unroll
            for (int off = 8; off; off >>= 1)
                tmax = fmaxf(tmax, __shfl_xor_sync(0xffffffffu, tmax, off));
            float newm = fmaxf(m[i], tmax);
            float alpha = __expf(m[i] - newm);
            float sum = 0.f;
#pragma unroll
            for (int j = 0; j < 4; j++) {
                float p = __expf(s[i][j] - newm);
                Ps[(tr * 4 + i) * 65 + tc * 4 + j] = p;
                sum += p;
            }
#pragma unroll
            for (int off = 8; off; off >>= 1)
                sum += __shfl_xor_sync(0xffffffffu, sum, off);
            l[i] = l[i] * alpha + sum;
            m[i] = newm;
#pragma unroll
            for (int j = 0; j < 8; j++) o[i][j] *= alpha;
        }
        __syncthreads();

        // O += P @ V
        for (int k = 0; k < 64; k++) {
            float pv[4];
#pragma unroll
            for (int i = 0; i < 4; i++) pv[i] = Ps[(tr * 4 + i) * 65 + k];
            float4 v0 = *(const float4*)&Vs[k * 128 + tc * 8];
            float4 v1 = *(const float4*)&Vs[k * 128 + tc * 8 + 4];
#pragma unroll
            for (int i = 0; i < 4; i++) {
                o[i][0] += pv[i] * v0.x; o[i][1] += pv[i] * v0.y;
                o[i][2] += pv[i] * v0.z; o[i][3] += pv[i] * v0.w;
                o[i][4] += pv[i] * v1.x; o[i][5] += pv[i] * v1.y;
                o[i][6] += pv[i] * v1.z; o[i][7] += pv[i] * v1.w;
            }
        }
    }

    // Normalize and store
#pragma unroll
    for (int i = 0; i < 4; i++) {
        float invl = 1.f / l[i];
        size_t row = (size_t)(qb * 64 + tr * 4 + i);
        float4 v0, v1;
        v0.x = o[i][0] * invl; v0.y = o[i][1] * invl;
        v0.z = o[i][2] * invl; v0.w = o[i][3] * invl;
        v1.x = o[i][4] * invl; v1.y = o[i][5] * invl;
        v1.z = o[i][6] * invl; v1.w = o[i][7] * invl;
        *(float4*)&attn[row * H + h * HD + tc * 8]     = v0;
        *(float4*)&attn[row * H + h * HD + tc * 8 + 4] = v1;
    }
}

// ---------------------------------------------------------------------------
// SiLU(gate) * up
// ---------------------------------------------------------------------------
__global__ void silu_kernel(const float* __restrict__ gu, float* __restrict__ hh) {
    int idx = blockIdx.x * 256 + threadIdx.x;
    if (idx >= SQ * II) return;
    int r = idx / II;
    int c = idx - r * II;
    float g = gu[(size_t)r * GUN + c];
    float u = gu[(size_t)r * GUN + II + c];
    hh[idx] = g / (1.f + expf(-g)) * u;
}

// ---------------------------------------------------------------------------
// Launch
// ---------------------------------------------------------------------------
template <typename T>
static float* sym_addr(T& symbol) {
    void* p = nullptr;
    cudaGetSymbolAddress(&p, symbol);
    return (float*)p;
}

extern "C" void kernel_launch(void* const* d_in, const int* in_sizes, int n_in,
                              void* d_out, int out_size) {
    const int*   positions = (const int*)d_in[0];
    const float* hidden    = (const float*)d_in[1];
    const float* w_qkv     = (const float*)d_in[2];
    const float* w_o       = (const float*)d_in[3];
    const float* w_gu      = (const float*)d_in[4];
    const float* w_down    = (const float*)d_in[5];
    const float* ln1       = (const float*)d_in[6];
    const float* ln2       = (const float*)d_in[7];
    float*       out       = (float*)d_out;

    float* xn   = sym_addr(g_xn);
    float* qkv  = sym_addr(g_qkv);
    float* attn = sym_addr(g_attn);
    float* xn2  = sym_addr(g_xn2);
    float* gu   = sym_addr(g_gu);
    float* hh   = sym_addr(g_hh);

    // residual output: second half of d_out (out, residual), else scratch
    float* resid = (out_size >= 2 * SQ * H) ? out + (size_t)SQ * H : sym_addr(g_res);

    cudaFuncSetAttribute(flash_kernel,
                         cudaFuncAttributeMaxDynamicSharedMemorySize, FA_SMEM);

    // 1. rmsnorm1
    rmsnorm_kernel<<<SQ, 256>>>(hidden, ln1, xn);
    // 2. qkv = xn @ w_qkv
    sgemm_kernel<0><<<dim3(QKVN / 128, SQ / 128), 256>>>(SQ, QKVN, H, xn, w_qkv, qkv, nullptr);
    // 3. rope (q and k, in place)
    rope_kernel<<<dim3(SQ, NQ + NKV), 64>>>(positions, qkv);
    // 4. causal GQA flash attention
    flash_kernel<<<dim3(SQ / 64, NQ), 256, FA_SMEM>>>(qkv, attn);
    // 5. residual = attn @ w_o + hidden
    sgemm_kernel<1><<<dim3(H / 128, SQ / 128), 256>>>(SQ, H, H, attn, w_o, resid, hidden);
    // 6. rmsnorm2
    rmsnorm_kernel<<<SQ, 256>>>(resid, ln2, xn2);
    // 7. gu = xn2 @ w_gate_up
    sgemm_kernel<0><<<dim3(GUN / 128, SQ / 128), 256>>>(SQ, GUN, H, xn2, w_gu, gu, nullptr);
    // 8. h = silu(gate) * up
    silu_kernel<<<(SQ * II + 255) / 256, 256>>>(gu, hh);
    // 9. out = h @ w_down
    sgemm_kernel<0><<<dim3(H / 128, SQ / 128), 256>>>(SQ, H, II, hh, w_down, out, nullptr);
}

// round 3
// speedup vs baseline: 3.2046x; 3.2046x over previous
#include <cuda_runtime.h>
#include <cstdint>
#include <math.h>

// Problem constants
#define SQ   2048
#define H    4096
#define NQ   32
#define NKV  8
#define HD   128
#define II   14336
#define QKVN (NQ*HD + 2*NKV*HD)   // 6144
#define GUN  (2*II)               // 28672

// ---------------------------------------------------------------------------
// Scratch (device globals; no allocation anywhere)
// ---------------------------------------------------------------------------
__device__ float g_xn   [SQ * H];
__device__ float g_qkv  [SQ * QKVN];
__device__ float g_attn [SQ * H];
__device__ float g_xn2  [SQ * H];
__device__ float g_gu   [(size_t)SQ * GUN];
__device__ float g_hh   [(size_t)SQ * II];
__device__ float g_res  [SQ * H];
// transposed + K-permuted + tf32-rounded weights
__device__ float g_wqkvT [(size_t)QKVN * H];
__device__ float g_woT   [(size_t)H * H];
__device__ float g_wguT  [(size_t)GUN * H];
__device__ float g_wdownT[(size_t)H * II];

// ---------------------------------------------------------------------------
// tf32 round helper
// ---------------------------------------------------------------------------
__device__ __forceinline__ float tf32r(float x) {
    uint32_t u;
    asm("cvt.rna.tf32.f32 %0, %1;" : "=r"(u) : "f"(x));
    return __uint_as_float(u);
}

// ---------------------------------------------------------------------------
// tf32 mma.sync GEMM: C[M,N] = A[M,K] @ Bt[N,K]^T  (+ optional residual)
// A and Bt are stored with per-8-block K permutation [0,4,1,5,2,6,3,7] and
// pre-rounded to tf32. 128x128x32 tiles, 4-stage cp.async pipeline.
// 256 threads = 8 warps in a 2(M) x 4(N) grid; each warp owns 64x32.
// ---------------------------------------------------------------------------
#define BM 128
#define BN 128
#define BK 32
#define STAGES 4
#define ROWB 160                    // (32 + 8 pad) floats * 4B
#define STAGE_A (128 * ROWB)        // 20480 B
#define STAGE_BYTES (2 * STAGE_A)   // 40960 B
#define GEMM_SMEM (STAGES * STAGE_BYTES)  // 163840 B

__device__ __forceinline__ void cp16(void* dst_smem, const void* src) {
    uint32_t d = (uint32_t)__cvta_generic_to_shared(dst_smem);
    asm volatile("cp.async.cg.shared.global [%0], [%1], 16;" :: "r"(d), "l"(src));
}
__device__ __forceinline__ void cp_commit() {
    asm volatile("cp.async.commit_group;" ::: "memory");
}
template <int N>
__device__ __forceinline__ void cp_wait() {
    asm volatile("cp.async.wait_group %0;" :: "n"(N) : "memory");
}
__device__ __forceinline__ void mma1688(float& c0, float& c1, float& c2, float& c3,
                                        uint32_t a0, uint32_t a1, uint32_t a2, uint32_t a3,
                                        uint32_t b0, uint32_t b1) {
    asm volatile(
        "mma.sync.aligned.m16n8k8.row.col.f32.tf32.tf32.f32 "
        "{%0,%1,%2,%3},{%4,%5,%6,%7},{%8,%9},{%0,%1,%2,%3};"
        : "+f"(c0), "+f"(c1), "+f"(c2), "+f"(c3)
        : "r"(a0), "r"(a1), "r"(a2), "r"(a3), "r"(b0), "r"(b1));
}

template <int ADD_RESID>
__global__ void __launch_bounds__(256, 1)
gemm_tf32_kernel(int M, int N, int K,
                 const float* __restrict__ A,
                 const float* __restrict__ Bt,
                 float* __restrict__ C,
                 const float* __restrict__ R) {
    extern __shared__ char sm[];

    const int tid  = threadIdx.x;
    const int wid  = tid >> 5;
    const int lane = tid & 31;
    const int wm   = wid >> 2;       // 0..1
    const int wn   = wid & 3;        // 0..3
    const int q    = lane & 3;
    const int g8   = lane >> 2;      // 0..7
    const int m0   = blockIdx.y * BM;
    const int n0   = blockIdx.x * BN;
    const int KT   = K >> 5;

    // per-thread load indices: 4 chunks of A, 4 chunks of B per stage
    const int lr = tid >> 3;         // base row 0..31 (then +32 per j)
    const int lc = tid & 7;          // 16B chunk 0..7

    auto load_stage = [&](int slot, int kt) {
        char* aS = sm + slot * STAGE_BYTES;
        char* bS = aS + STAGE_A;
        const float* Ag = A  + (size_t)m0 * K + (size_t)kt * 32;
        const float* Bg = Bt + (size_t)n0 * K + (size_t)kt * 32;
#pragma unroll
        for (int j = 0; j < 4; j++) {
            int r = lr + j * 32;
            cp16(aS + r * ROWB + lc * 16, Ag + (size_t)r * K + lc * 4);
            cp16(bS + r * ROWB + lc * 16, Bg + (size_t)r * K + lc * 4);
        }
    };

    // prologue
#pragma unroll
    for (int s = 0; s < STAGES - 1; s++) {
        load_stage(s, s);
        cp_commit();
    }

    float acc[4][4][4];
#pragma unroll
    for (int mt = 0; mt < 4; mt++)
#pragma unroll
        for (int nt = 0; nt < 4; nt++)
#pragma unroll
            for (int c = 0; c < 4; c++) acc[mt][nt][c] = 0.f;

    for (int kt = 0; kt < KT; kt++) {
        cp_wait<STAGES - 2>();
        __syncthreads();

        int nk = kt + STAGES - 1;
        if (nk < KT) load_stage(nk % STAGES, nk);
        cp_commit();

        char* aS = sm + (kt % STAGES) * STAGE_BYTES;
        char* bS = aS + STAGE_A;

#pragma unroll
        for (int ks = 0; ks < 4; ks++) {
            int fo = ks * 32 + q * 8;   // byte offset of this thread's frag pair
            float2 bf[4];
#pragma unroll
            for (int nt = 0; nt < 4; nt++)
                bf[nt] = *(const float2*)(bS + (wn * 32 + nt * 8 + g8) * ROWB + fo);
#pragma unroll
            for (int mt = 0; mt < 4; mt++) {
                int row = wm * 64 + mt * 16 + g8;
                float2 aL = *(const float2*)(aS + row * ROWB + fo);
                float2 aH = *(const float2*)(aS + (row + 8) * ROWB + fo);
                uint32_t a0 = __float_as_uint(aL.x);
                uint32_t a1 = __float_as_uint(aH.x);
                uint32_t a2 = __float_as_uint(aL.y);
                uint32_t a3 = __float_as_uint(aH.y);
#pragma unroll
                for (int nt = 0; nt < 4; nt++)
                    mma1688(acc[mt][nt][0], acc[mt][nt][1], acc[mt][nt][2], acc[mt][nt][3],
                            a0, a1, a2, a3,
                            __float_as_uint(bf[nt].x), __float_as_uint(bf[nt].y));
            }
        }
        __syncthreads();
    }

    // epilogue
#pragma unroll
    for (int mt = 0; mt < 4; mt++) {
        int r0 = m0 + wm * 64 + mt * 16 + g8;
#pragma unroll
        for (int nt = 0; nt < 4; nt++) {
            int cc = n0 + wn * 32 + nt * 8 + 2 * q;
            float2 v0 = make_float2(acc[mt][nt][0], acc[mt][nt][1]);
            float2 v1 = make_float2(acc[mt][nt][2], acc[mt][nt][3]);
            if (ADD_RESID) {
                float2 r = *(const float2*)&R[(size_t)r0 * N + cc];
                v0.x += r.x; v0.y += r.y;
                r = *(const float2*)&R[(size_t)(r0 + 8) * N + cc];
                v1.x += r.x; v1.y += r.y;
            }
            *(float2*)&C[(size_t)r0 * N + cc]       = v0;
            *(float2*)&C[(size_t)(r0 + 8) * N + cc] = v1;
        }
    }
}

// ---------------------------------------------------------------------------
// Weight transpose: out[n][perm(k)] = tf32(in[k][n])
// ---------------------------------------------------------------------------
__global__ void transpose_kernel(const float* __restrict__ in, float* __restrict__ out,
                                 int Kd, int Nd) {
    __shared__ float tile[32][33];
    int k0 = blockIdx.y * 32, n0 = blockIdx.x * 32;
    int tx = threadIdx.x;
#pragma unroll
    for (int i = threadIdx.y; i < 32; i += 8)
        tile[i][tx] = in[(size_t)(k0 + i) * Nd + n0 + tx];
    __syncthreads();
    int pk = (tx & ~7) | (((tx & 3) << 1) | ((tx >> 2) & 1));
#pragma unroll
    for (int i = threadIdx.y; i < 32; i += 8)
        out[(size_t)(n0 + i) * Kd + k0 + pk] = tf32r(tile[tx][i]);
}

// ---------------------------------------------------------------------------
// RMSNorm -> tf32-rounded, K-permuted output (GEMM A operand)
// ---------------------------------------------------------------------------
__global__ void rmsnorm_perm_kernel(const float* __restrict__ x,
                                    const float* __restrict__ w,
                                    float* __restrict__ y) {
    int row = blockIdx.x;
    const float4* xr = (const float4*)(x + (size_t)row * H);
    float4*       yr = (float4*)(y + (size_t)row * H);
    const float4* wv = (const float4*)w;

    float s = 0.f;
    for (int i = threadIdx.x; i < H / 4; i += 256) {
        float4 v = xr[i];
        s += v.x * v.x + v.y * v.y + v.z * v.z + v.w * v.w;
    }
    __shared__ float red[256];
    red[threadIdx.x] = s;
    __syncthreads();
    for (int off = 128; off; off >>= 1) {
        if (threadIdx.x < off) red[threadIdx.x] += red[threadIdx.x + off];
        __syncthreads();
    }
    float inv = rsqrtf(red[0] / (float)H + 1e-5f);

    for (int i = threadIdx.x; i < H / 8; i += 256) {
        float4 v0 = xr[2 * i], v1 = xr[2 * i + 1];
        float4 g0 = wv[2 * i], g1 = wv[2 * i + 1];
        float y0 = tf32r(v0.x * inv * g0.x), y1 = tf32r(v0.y * inv * g0.y);
        float y2 = tf32r(v0.z * inv * g0.z), y3 = tf32r(v0.w * inv * g0.w);
        float y4 = tf32r(v1.x * inv * g1.x), y5 = tf32r(v1.y * inv * g1.y);
        float y6 = tf32r(v1.z * inv * g1.z), y7 = tf32r(v1.w * inv * g1.w);
        yr[2 * i]     = make_float4(y0, y4, y1, y5);
        yr[2 * i + 1] = make_float4(y2, y6, y3, y7);
    }
}

// ---------------------------------------------------------------------------
// RoPE (in place on q/k of qkv, normal layout)
// ---------------------------------------------------------------------------
__global__ void rope_kernel(const int* __restrict__ pos, float* __restrict__ qkv) {
    int s  = blockIdx.x;
    int hh = blockIdx.y;
    int i  = threadIdx.x;
    int base = (hh < NQ) ? hh * HD : NQ * HD + (hh - NQ) * HD;
    float* p = qkv + (size_t)s * QKVN + base;

    float fpos = (float)pos[s];
    float invf = powf(10000.0f, -(float)i / 64.0f);
    float ang  = fpos * invf;
    float sn, cs;
    sincosf(ang, &sn, &cs);
    float x1 = p[i], x2 = p[i + 64];
    p[i]      = x1 * cs - x2 * sn;
    p[i + 64] = x2 * cs + x1 * sn;
}

// ---------------------------------------------------------------------------
// Flash attention (causal, GQA G=4), fp32; output tf32-rounded + K-permuted
// ---------------------------------------------------------------------------
#define FA_QS   (64 * 128)
#define FA_KS   (64 * 132)
#define FA_VS   (64 * 128)
#define FA_PS   (64 * 65)
#define FA_SMEM ((FA_QS + FA_KS + FA_VS + FA_PS) * 4)

__global__ void __launch_bounds__(256)
flash_kernel(const float* __restrict__ qkv, float* __restrict__ attn) {
    extern __shared__ float smf[];
    float* Qs = smf;
    float* Ks = Qs + FA_QS;
    float* Vs = Ks + FA_KS;
    float* Ps = Vs + FA_VS;

    const int qb  = blockIdx.x;
    const int h   = blockIdx.y;
    const int kh  = h >> 2;
    const int tid = threadIdx.x;
    const int tc  = tid & 15;
    const int tr  = tid >> 4;
    const float scale = 0.08838834764831845f;

    for (int i = tid; i < 64 * 32; i += 256) {
        int r  = i >> 5;
        int c4 = (i & 31) << 2;
        float4 v = *(const float4*)&qkv[(size_t)(qb * 64 + r) * QKVN + h * HD + c4];
        v.x *= scale; v.y *= scale; v.z *= scale; v.w *= scale;
        *(float4*)&Qs[r * 128 + c4] = v;
    }

    float o[4][8];
    float m[4], l[4];
#pragma unroll
    for (int i = 0; i < 4; i++) {
        m[i] = -1e30f; l[i] = 0.f;
#pragma unroll
        for (int j = 0; j < 8; j++) o[i][j] = 0.f;
    }

    for (int jt = 0; jt <= qb; jt++) {
        __syncthreads();
        for (int i = tid; i < 64 * 32; i += 256) {
            int r  = i >> 5;
            int c4 = (i & 31) << 2;
            size_t rowoff = (size_t)(jt * 64 + r) * QKVN;
            float4 kv = *(const float4*)&qkv[rowoff + NQ * HD + kh * HD + c4];
            *(float4*)&Ks[r * 132 + c4] = kv;
            float4 vv = *(const float4*)&qkv[rowoff + (NQ + NKV) * HD + kh * HD + c4];
            *(float4*)&Vs[r * 128 + c4] = vv;
        }
        __syncthreads();

        float s[4][4];
#pragma unroll
        for (int i = 0; i < 4; i++)
#pragma unroll
            for (int j = 0; j < 4; j++) s[i][j] = 0.f;

        for (int d = 0; d < 128; d += 4) {
            float4 qv[4], kv[4];
#pragma unroll
            for (int i = 0; i < 4; i++)
                qv[i] = *(const float4*)&Qs[(tr * 4 + i) * 128 + d];
#pragma unroll
            for (int j = 0; j < 4; j++)
                kv[j] = *(const float4*)&Ks[(tc * 4 + j) * 132 + d];
#pragma unroll
            for (int i = 0; i < 4; i++)
#pragma unroll
                for (int j = 0; j < 4; j++)
                    s[i][j] += qv[i].x * kv[j].x + qv[i].y * kv[j].y +
                               qv[i].z * kv[j].z + qv[i].w * kv[j].w;
        }

        if (jt == qb) {
#pragma unroll
            for (int i = 0; i < 4; i++) {
                int rl = tr * 4 + i;
#pragma unroll
                for (int j = 0; j < 4; j++) {
                    int cl = tc * 4 + j;
                    if (cl > rl) s[i][j] = -1e30f;
                }
            }
        }

#pragma unroll
        for (int i = 0; i < 4; i++) {
            float tmax = fmaxf(fmaxf(s[i][0], s[i][1]), fmaxf(s[i][2], s[i][3]));
#pragma unroll
            for (int off = 8; off; off >>= 1)
                tmax = fmaxf(tmax, __shfl_xor_sync(0xffffffffu, tmax, off));
            float newm = fmaxf(m[i], tmax);
            float alpha = __expf(m[i] - newm);
            float sum = 0.f;
#pragma unroll
            for (int j = 0; j < 4; j++) {
                float p = __expf(s[i][j] - newm);
                Ps[(tr * 4 + i) * 65 + tc * 4 + j] = p;
                sum += p;
            }
#pragma unroll
            for (int off = 8; off; off >>= 1)
                sum += __shfl_xor_sync(0xffffffffu, sum, off);
            l[i] = l[i] * alpha + sum;
            m[i] = newm;
#pragma unroll
            for (int j = 0; j < 8; j++) o[i][j] *= alpha;
        }
        __syncthreads();

        for (int k = 0; k < 64; k++) {
            float pv[4];
#pragma unroll
            for (int i = 0; i < 4; i++) pv[i] = Ps[(tr * 4 + i) * 65 + k];
            float4 v0 = *(const float4*)&Vs[k * 128 + tc * 8];
            float4 v1 = *(const float4*)&Vs[k * 128 + tc * 8 + 4];
#pragma unroll
            for (int i = 0; i < 4; i++) {
                o[i][0] += pv[i] * v0.x; o[i][1] += pv[i] * v0.y;
                o[i][2] += pv[i] * v0.z; o[i][3] += pv[i] * v0.w;
                o[i][4] += pv[i] * v1.x; o[i][5] += pv[i] * v1.y;
                o[i][6] += pv[i] * v1.z; o[i][7] += pv[i] * v1.w;
            }
        }
    }

    // Normalize, tf32-round, permute-write [o0,o4,o1,o5,o2,o6,o3,o7]
#pragma unroll
    for (int i = 0; i < 4; i++) {
        float invl = 1.f / l[i];
        size_t row = (size_t)(qb * 64 + tr * 4 + i);
        float y0 = tf32r(o[i][0] * invl), y1 = tf32r(o[i][1] * invl);
        float y2 = tf32r(o[i][2] * invl), y3 = tf32r(o[i][3] * invl);
        float y4 = tf32r(o[i][4] * invl), y5 = tf32r(o[i][5] * invl);
        float y6 = tf32r(o[i][6] * invl), y7 = tf32r(o[i][7] * invl);
        *(float4*)&attn[row * H + h * HD + tc * 8]     = make_float4(y0, y4, y1, y5);
        *(float4*)&attn[row * H + h * HD + tc * 8 + 4] = make_float4(y2, y6, y3, y7);
    }
}

// ---------------------------------------------------------------------------
// SiLU(gate) * up -> tf32-rounded, K-permuted output
// ---------------------------------------------------------------------------
__global__ void silu_perm_kernel(const float* __restrict__ gu, float* __restrict__ hh) {
    int idx = blockIdx.x * 256 + threadIdx.x;       // per 8 elems
    if (idx >= SQ * II / 8) return;
    int r = idx / (II / 8);
    int c = (idx - r * (II / 8)) * 8;
    const float* gp = gu + (size_t)r * GUN + c;
    const float* up = gu + (size_t)r * GUN + II + c;
    float4 ga = *(const float4*)gp, gb = *(const float4*)(gp + 4);
    float4 ua = *(const float4*)up, ub = *(const float4*)(up + 4);
    float y0 = tf32r(ga.x / (1.f + __expf(-ga.x)) * ua.x);
    float y1 = tf32r(ga.y / (1.f + __expf(-ga.y)) * ua.y);
    float y2 = tf32r(ga.z / (1.f + __expf(-ga.z)) * ua.z);
    float y3 = tf32r(ga.w / (1.f + __expf(-ga.w)) * ua.w);
    float y4 = tf32r(gb.x / (1.f + __expf(-gb.x)) * ub.x);
    float y5 = tf32r(gb.y / (1.f + __expf(-gb.y)) * ub.y);
    float y6 = tf32r(gb.z / (1.f + __expf(-gb.z)) * ub.z);
    float y7 = tf32r(gb.w / (1.f + __expf(-gb.w)) * ub.w);
    float* op = hh + (size_t)r * II + c;
    *(float4*)op       = make_float4(y0, y4, y1, y5);
    *(float4*)(op + 4) = make_float4(y2, y6, y3, y7);
}

// ---------------------------------------------------------------------------
// Launch
// ---------------------------------------------------------------------------
template <typename T>
static float* sym_addr(T& symbol) {
    void* p = nullptr;
    cudaGetSymbolAddress(&p, symbol);
    return (float*)p;
}

extern "C" void kernel_launch(void* const* d_in, const int* in_sizes, int n_in,
                              void* d_out, int out_size) {
    const int*   positions = (const int*)d_in[0];
    const float* hidden    = (const float*)d_in[1];
    const float* w_qkv     = (const float*)d_in[2];
    const float* w_o       = (const float*)d_in[3];
    const float* w_gu      = (const float*)d_in[4];
    const float* w_down    = (const float*)d_in[5];
    const float* ln1       = (const float*)d_in[6];
    const float* ln2       = (const float*)d_in[7];
    float*       out       = (float*)d_out;

    float* xn     = sym_addr(g_xn);
    float* qkv    = sym_addr(g_qkv);
    float* attn   = sym_addr(g_attn);
    float* xn2    = sym_addr(g_xn2);
    float* gu     = sym_addr(g_gu);
    float* hh     = sym_addr(g_hh);
    float* wqkvT  = sym_addr(g_wqkvT);
    float* woT    = sym_addr(g_woT);
    float* wguT   = sym_addr(g_wguT);
    float* wdownT = sym_addr(g_wdownT);

    float* resid = (out_size >= 2 * SQ * H) ? out + (size_t)SQ * H : sym_addr(g_res);

    cudaFuncSetAttribute(flash_kernel, cudaFuncAttributeMaxDynamicSharedMemorySize, FA_SMEM);
    cudaFuncSetAttribute(gemm_tf32_kernel<0>, cudaFuncAttributeMaxDynamicSharedMemorySize, GEMM_SMEM);
    cudaFuncSetAttribute(gemm_tf32_kernel<1>, cudaFuncAttributeMaxDynamicSharedMemorySize, GEMM_SMEM);

    // 0. weight transposes (tf32 + K-permuted)
    transpose_kernel<<<dim3(QKVN / 32, H / 32),  dim3(32, 8)>>>(w_qkv,  wqkvT,  H,  QKVN);
    transpose_kernel<<<dim3(H / 32,    H / 32),  dim3(32, 8)>>>(w_o,    woT,    H,  H);
    transpose_kernel<<<dim3(GUN / 32,  H / 32),  dim3(32, 8)>>>(w_gu,   wguT,   H,  GUN);
    transpose_kernel<<<dim3(H / 32,   II / 32),  dim3(32, 8)>>>(w_down, wdownT, II, H);

    // 1. rmsnorm1 (permuted output)
    rmsnorm_perm_kernel<<<SQ, 256>>>(hidden, ln1, xn);
    // 2. qkv = xn @ w_qkv
    gemm_tf32_kernel<0><<<dim3(QKVN / 128, SQ / 128), 256, GEMM_SMEM>>>(SQ, QKVN, H, xn, wqkvT, qkv, nullptr);
    // 3. rope
    rope_kernel<<<dim3(SQ, NQ + NKV), 64>>>(positions, qkv);
    // 4. flash attention (permuted output)
    flash_kernel<<<dim3(SQ / 64, NQ), 256, FA_SMEM>>>(qkv, attn);
    // 5. residual = attn @ w_o + hidden
    gemm_tf32_kernel<1><<<dim3(H / 128, SQ / 128), 256, GEMM_SMEM>>>(SQ, H, H, attn, woT, resid, hidden);
    // 6. rmsnorm2 (permuted output)
    rmsnorm_perm_kernel<<<SQ, 256>>>(resid, ln2, xn2);
    // 7. gu = xn2 @ w_gate_up
    gemm_tf32_kernel<0><<<dim3(GUN / 128, SQ / 128), 256, GEMM_SMEM>>>(SQ, GUN, H, xn2, wguT, gu, nullptr);
    // 8. h = silu(gate)*up (permuted output)
    silu_perm_kernel<<<(SQ * II / 8 + 255) / 256, 256>>>(gu, hh);
    // 9. out = h @ w_down
    gemm_tf32_kernel<0><<<dim3(H / 128, SQ / 128), 256, GEMM_SMEM>>>(SQ, H, II, hh, wdownT, out, nullptr);
}

// round 4
// speedup vs baseline: 3.9714x; 1.2393x over previous
#include <cuda_runtime.h>
#include <cstdint>
#include <math.h>

// Problem constants
#define SQ   2048
#define H    4096
#define NQ   32
#define NKV  8
#define HD   128
#define II   14336
#define QKVN (NQ*HD + 2*NKV*HD)   // 6144
#define GUN  (2*II)               // 28672

// ---------------------------------------------------------------------------
// Scratch (device globals; no allocation anywhere)
// ---------------------------------------------------------------------------
__device__ float g_xn   [SQ * H];
__device__ float g_qkv  [SQ * QKVN];
__device__ float g_attn [SQ * H];
__device__ float g_xn2  [SQ * H];
__device__ float g_hh   [(size_t)SQ * II];
__device__ float g_res  [SQ * H];
__device__ float g_wqkvT [(size_t)QKVN * H];
__device__ float g_woT   [(size_t)H * H];
__device__ float g_wguT  [(size_t)GUN * H];
__device__ float g_wdownT[(size_t)H * II];

// ---------------------------------------------------------------------------
// Helpers
// ---------------------------------------------------------------------------
__device__ __forceinline__ float tf32r(float x) {
    uint32_t u;
    asm("cvt.rna.tf32.f32 %0, %1;" : "=r"(u) : "f"(x));
    return __uint_as_float(u);
}
__device__ __forceinline__ void cp16(void* dst_smem, const void* src) {
    uint32_t d = (uint32_t)__cvta_generic_to_shared(dst_smem);
    asm volatile("cp.async.cg.shared.global [%0], [%1], 16;" :: "r"(d), "l"(src));
}
__device__ __forceinline__ void cp_commit() {
    asm volatile("cp.async.commit_group;" ::: "memory");
}
template <int N>
__device__ __forceinline__ void cp_wait() {
    asm volatile("cp.async.wait_group %0;" :: "n"(N) : "memory");
}
__device__ __forceinline__ void mma1688(float& c0, float& c1, float& c2, float& c3,
                                        uint32_t a0, uint32_t a1, uint32_t a2, uint32_t a3,
                                        uint32_t b0, uint32_t b1) {
    asm volatile(
        "mma.sync.aligned.m16n8k8.row.col.f32.tf32.tf32.f32 "
        "{%0,%1,%2,%3},{%4,%5,%6,%7},{%8,%9},{%0,%1,%2,%3};"
        : "+f"(c0), "+f"(c1), "+f"(c2), "+f"(c3)
        : "r"(a0), "r"(a1), "r"(a2), "r"(a3), "r"(b0), "r"(b1));
}

// ---------------------------------------------------------------------------
// tf32 mma GEMM: C[M,N] = A[M,K] @ Bt[N,K]^T (+residual). A, Bt K-permuted tf32.
// 128x128x32 tiles, 4-stage cp.async pipeline, 8 warps (2x4 of 64x32).
// ---------------------------------------------------------------------------
#define STAGES 4
#define ROWB 160
#define STAGE_A (128 * ROWB)
#define STAGE_BYTES (2 * STAGE_A)
#define GEMM_SMEM (STAGES * STAGE_BYTES)

template <int ADD_RESID>
__global__ void __launch_bounds__(256, 1)
gemm_tf32_kernel(int M, int N, int K,
                 const float* __restrict__ A,
                 const float* __restrict__ Bt,
                 float* __restrict__ C,
                 const float* __restrict__ R) {
    extern __shared__ char sm[];

    const int tid  = threadIdx.x;
    const int wid  = tid >> 5;
    const int lane = tid & 31;
    const int wm   = wid >> 2;
    const int wn   = wid & 3;
    const int q    = lane & 3;
    const int g8   = lane >> 2;
    const int m0   = blockIdx.y * 128;
    const int n0   = blockIdx.x * 128;
    const int KT   = K >> 5;

    const int lr = tid >> 3;
    const int lc = tid & 7;

    auto load_stage = [&](int slot, int kt) {
        char* aS = sm + slot * STAGE_BYTES;
        char* bS = aS + STAGE_A;
        const float* Ag = A  + (size_t)m0 * K + (size_t)kt * 32;
        const float* Bg = Bt + (size_t)n0 * K + (size_t)kt * 32;
#pragma unroll
        for (int j = 0; j < 4; j++) {
            int r = lr + j * 32;
            cp16(aS + r * ROWB + lc * 16, Ag + (size_t)r * K + lc * 4);
            cp16(bS + r * ROWB + lc * 16, Bg + (size_t)r * K + lc * 4);
        }
    };

#pragma unroll
    for (int s = 0; s < STAGES - 1; s++) {
        load_stage(s, s);
        cp_commit();
    }

    float acc[4][4][4];
#pragma unroll
    for (int mt = 0; mt < 4; mt++)
#pragma unroll
        for (int nt = 0; nt < 4; nt++)
#pragma unroll
            for (int c = 0; c < 4; c++) acc[mt][nt][c] = 0.f;

    for (int kt = 0; kt < KT; kt++) {
        cp_wait<STAGES - 2>();
        __syncthreads();

        int nk = kt + STAGES - 1;
        if (nk < KT) load_stage(nk % STAGES, nk);
        cp_commit();

        char* aS = sm + (kt % STAGES) * STAGE_BYTES;
        char* bS = aS + STAGE_A;

#pragma unroll
        for (int ks = 0; ks < 4; ks++) {
            int fo = ks * 32 + q * 8;
            float2 bf[4];
#pragma unroll
            for (int nt = 0; nt < 4; nt++)
                bf[nt] = *(const float2*)(bS + (wn * 32 + nt * 8 + g8) * ROWB + fo);
#pragma unroll
            for (int mt = 0; mt < 4; mt++) {
                int row = wm * 64 + mt * 16 + g8;
                float2 aL = *(const float2*)(aS + row * ROWB + fo);
                float2 aH = *(const float2*)(aS + (row + 8) * ROWB + fo);
                uint32_t a0 = __float_as_uint(aL.x);
                uint32_t a1 = __float_as_uint(aH.x);
                uint32_t a2 = __float_as_uint(aL.y);
                uint32_t a3 = __float_as_uint(aH.y);
#pragma unroll
                for (int nt = 0; nt < 4; nt++)
                    mma1688(acc[mt][nt][0], acc[mt][nt][1], acc[mt][nt][2], acc[mt][nt][3],
                            a0, a1, a2, a3,
                            __float_as_uint(bf[nt].x), __float_as_uint(bf[nt].y));
            }
        }
        // no bottom barrier: top barrier protects slot reuse (3 iters later)
    }

#pragma unroll
    for (int mt = 0; mt < 4; mt++) {
        int r0 = m0 + wm * 64 + mt * 16 + g8;
#pragma unroll
        for (int nt = 0; nt < 4; nt++) {
            int cc = n0 + wn * 32 + nt * 8 + 2 * q;
            float2 v0 = make_float2(acc[mt][nt][0], acc[mt][nt][1]);
            float2 v1 = make_float2(acc[mt][nt][2], acc[mt][nt][3]);
            if (ADD_RESID) {
                float2 r = *(const float2*)&R[(size_t)r0 * N + cc];
                v0.x += r.x; v0.y += r.y;
                r = *(const float2*)&R[(size_t)(r0 + 8) * N + cc];
                v1.x += r.x; v1.y += r.y;
            }
            *(float2*)&C[(size_t)r0 * N + cc]       = v0;
            *(float2*)&C[(size_t)(r0 + 8) * N + cc] = v1;
        }
    }
}

// ---------------------------------------------------------------------------
// Fused gate/up GEMM + SiLU: hh[M,II] = tf32perm(silu(A@Wg) * (A@Wu))
// Dual accumulators, 3-stage pipeline. BtG rows [0,II), BtU rows [II,2II).
// ---------------------------------------------------------------------------
#define FSTAGES 3
#define FSTAGE_BYTES (3 * STAGE_A)
#define FGU_SMEM (FSTAGES * FSTAGE_BYTES)

__global__ void __launch_bounds__(256, 1)
gemm_gateup_silu_kernel(int M, int K,
                        const float* __restrict__ A,
                        const float* __restrict__ Bt,   // [GUN][K]
                        float* __restrict__ HHout) {
    extern __shared__ char sm[];

    const int tid  = threadIdx.x;
    const int wid  = tid >> 5;
    const int lane = tid & 31;
    const int wm   = wid >> 2;
    const int wn   = wid & 3;
    const int q    = lane & 3;
    const int g8   = lane >> 2;
    const int m0   = blockIdx.y * 128;
    const int n0   = blockIdx.x * 128;
    const int KT   = K >> 5;

    const int lr = tid >> 3;
    const int lc = tid & 7;

    const float* BG = Bt + (size_t)n0 * K;
    const float* BU = Bt + (size_t)(II + n0) * K;

    auto load_stage = [&](int slot, int kt) {
        char* aS = sm + slot * FSTAGE_BYTES;
        char* gS = aS + STAGE_A;
        char* uS = gS + STAGE_A;
        const float* Ag = A + (size_t)m0 * K + (size_t)kt * 32;
        const float* Gg = BG + (size_t)kt * 32;
        const float* Ug = BU + (size_t)kt * 32;
#pragma unroll
        for (int j = 0; j < 4; j++) {
            int r = lr + j * 32;
            cp16(aS + r * ROWB + lc * 16, Ag + (size_t)r * K + lc * 4);
            cp16(gS + r * ROWB + lc * 16, Gg + (size_t)r * K + lc * 4);
            cp16(uS + r * ROWB + lc * 16, Ug + (size_t)r * K + lc * 4);
        }
    };

#pragma unroll
    for (int s = 0; s < FSTAGES - 1; s++) {
        load_stage(s, s);
        cp_commit();
    }

    float accG[4][4][4], accU[4][4][4];
#pragma unroll
    for (int mt = 0; mt < 4; mt++)
#pragma unroll
        for (int nt = 0; nt < 4; nt++)
#pragma unroll
            for (int c = 0; c < 4; c++) { accG[mt][nt][c] = 0.f; accU[mt][nt][c] = 0.f; }

    for (int kt = 0; kt < KT; kt++) {
        cp_wait<FSTAGES - 2>();
        __syncthreads();

        int nk = kt + FSTAGES - 1;
        if (nk < KT) load_stage(nk % FSTAGES, nk);
        cp_commit();

        char* aS = sm + (kt % FSTAGES) * FSTAGE_BYTES;
        char* gS = aS + STAGE_A;
        char* uS = gS + STAGE_A;

#pragma unroll
        for (int ks = 0; ks < 4; ks++) {
            int fo = ks * 32 + q * 8;
            float2 bg[4], bu[4];
#pragma unroll
            for (int nt = 0; nt < 4; nt++) {
                int roff = (wn * 32 + nt * 8 + g8) * ROWB + fo;
                bg[nt] = *(const float2*)(gS + roff);
                bu[nt] = *(const float2*)(uS + roff);
            }
#pragma unroll
            for (int mt = 0; mt < 4; mt++) {
                int row = wm * 64 + mt * 16 + g8;
                float2 aL = *(const float2*)(aS + row * ROWB + fo);
                float2 aH = *(const float2*)(aS + (row + 8) * ROWB + fo);
                uint32_t a0 = __float_as_uint(aL.x);
                uint32_t a1 = __float_as_uint(aH.x);
                uint32_t a2 = __float_as_uint(aL.y);
                uint32_t a3 = __float_as_uint(aH.y);
#pragma unroll
                for (int nt = 0; nt < 4; nt++) {
                    mma1688(accG[mt][nt][0], accG[mt][nt][1], accG[mt][nt][2], accG[mt][nt][3],
                            a0, a1, a2, a3,
                            __float_as_uint(bg[nt].x), __float_as_uint(bg[nt].y));
                    mma1688(accU[mt][nt][0], accU[mt][nt][1], accU[mt][nt][2], accU[mt][nt][3],
                            a0, a1, a2, a3,
                            __float_as_uint(bu[nt].x), __float_as_uint(bu[nt].y));
                }
            }
        }
    }

    // epilogue: silu(g)*u, tf32-rounded, K-permuted write
    const int pp0 = (q < 2) ? 4 * q : 4 * q - 7;       // perm of logical 2q
    const int pp1 = (q < 2) ? 4 * q + 2 : 4 * q - 5;   // perm of logical 2q+1
#pragma unroll
    for (int mt = 0; mt < 4; mt++) {
        size_t r0 = (size_t)(m0 + wm * 64 + mt * 16 + g8);
        size_t r1 = r0 + 8;
#pragma unroll
        for (int nt = 0; nt < 4; nt++) {
            int gb = n0 + wn * 32 + nt * 8;
            float g0 = accG[mt][nt][0], g1 = accG[mt][nt][1];
            float g2 = accG[mt][nt][2], g3 = accG[mt][nt][3];
            float u0 = accU[mt][nt][0], u1 = accU[mt][nt][1];
            float u2 = accU[mt][nt][2], u3 = accU[mt][nt][3];
            HHout[r0 * II + gb + pp0] = tf32r(g0 / (1.f + __expf(-g0)) * u0);
            HHout[r0 * II + gb + pp1] = tf32r(g1 / (1.f + __expf(-g1)) * u1);
            HHout[r1 * II + gb + pp0] = tf32r(g2 / (1.f + __expf(-g2)) * u2);
            HHout[r1 * II + gb + pp1] = tf32r(g3 / (1.f + __expf(-g3)) * u3);
        }
    }
}

// ---------------------------------------------------------------------------
// Weight transpose: out[n][perm(k)] = tf32(in[k][n])
// ---------------------------------------------------------------------------
__global__ void transpose_kernel(const float* __restrict__ in, float* __restrict__ out,
                                 int Kd, int Nd) {
    __shared__ float tile[32][33];
    int k0 = blockIdx.y * 32, n0 = blockIdx.x * 32;
    int tx = threadIdx.x;
#pragma unroll
    for (int i = threadIdx.y; i < 32; i += 8)
        tile[i][tx] = in[(size_t)(k0 + i) * Nd + n0 + tx];
    __syncthreads();
    int pk = (tx & ~7) | (((tx & 3) << 1) | ((tx >> 2) & 1));
#pragma unroll
    for (int i = threadIdx.y; i < 32; i += 8)
        out[(size_t)(n0 + i) * Kd + k0 + pk] = tf32r(tile[tx][i]);
}

// ---------------------------------------------------------------------------
// RMSNorm -> tf32 K-permuted output
// ---------------------------------------------------------------------------
__global__ void rmsnorm_perm_kernel(const float* __restrict__ x,
                                    const float* __restrict__ w,
                                    float* __restrict__ y) {
    int row = blockIdx.x;
    const float4* xr = (const float4*)(x + (size_t)row * H);
    float4*       yr = (float4*)(y + (size_t)row * H);
    const float4* wv = (const float4*)w;

    float s = 0.f;
    for (int i = threadIdx.x; i < H / 4; i += 256) {
        float4 v = xr[i];
        s += v.x * v.x + v.y * v.y + v.z * v.z + v.w * v.w;
    }
    __shared__ float red[256];
    red[threadIdx.x] = s;
    __syncthreads();
    for (int off = 128; off; off >>= 1) {
        if (threadIdx.x < off) red[threadIdx.x] += red[threadIdx.x + off];
        __syncthreads();
    }
    float inv = rsqrtf(red[0] / (float)H + 1e-5f);

    for (int i = threadIdx.x; i < H / 8; i += 256) {
        float4 v0 = xr[2 * i], v1 = xr[2 * i + 1];
        float4 g0 = wv[2 * i], g1 = wv[2 * i + 1];
        float y0 = tf32r(v0.x * inv * g0.x), y1 = tf32r(v0.y * inv * g0.y);
        float y2 = tf32r(v0.z * inv * g0.z), y3 = tf32r(v0.w * inv * g0.w);
        float y4 = tf32r(v1.x * inv * g1.x), y5 = tf32r(v1.y * inv * g1.y);
        float y6 = tf32r(v1.z * inv * g1.z), y7 = tf32r(v1.w * inv * g1.w);
        yr[2 * i]     = make_float4(y0, y4, y1, y5);
        yr[2 * i + 1] = make_float4(y2, y6, y3, y7);
    }
}

// ---------------------------------------------------------------------------
// RoPE (in place on q/k of qkv)
// ---------------------------------------------------------------------------
__global__ void rope_kernel(const int* __restrict__ pos, float* __restrict__ qkv) {
    int s  = blockIdx.x;
    int hh = blockIdx.y;
    int i  = threadIdx.x;
    int base = (hh < NQ) ? hh * HD : NQ * HD + (hh - NQ) * HD;
    float* p = qkv + (size_t)s * QKVN + base;

    float fpos = (float)pos[s];
    float invf = powf(10000.0f, -(float)i / 64.0f);
    float ang  = fpos * invf;
    float sn, cs;
    sincosf(ang, &sn, &cs);
    float x1 = p[i], x2 = p[i + 64];
    p[i]      = x1 * cs - x2 * sn;
    p[i + 64] = x2 * cs + x1 * sn;
}

// ---------------------------------------------------------------------------
// Tensor-core flash attention (causal, GQA G=4), tf32 mma.
// Block: 256 threads (8 warps), 128 q-rows, one head. KV tiles of 64.
// Warp w owns rows 16w..16w+15 (softmax rows never cross warps).
// Qs/Ks: K-permuted tf32 (frag float2 loads). Vt: V transposed [hd][perm key].
// Ps: P [row][perm key]. Output tf32-rounded + permuted (feeds w_o GEMM).
// ---------------------------------------------------------------------------
#define FPQ 132
#define FPV 68
#define FPP 72
#define OFF_KS (128 * FPQ)                 // 16896
#define OFF_VT (OFF_KS + 64 * FPQ)         // 25344
#define OFF_PS (OFF_VT + 128 * FPV)        // 34048
#define FA2_SMEM ((OFF_PS + 128 * FPP) * 4)  // 173056 B

__global__ void __launch_bounds__(256, 1)
flash2_kernel(const float* __restrict__ qkv, float* __restrict__ attn) {
    extern __shared__ float sf[];
    float* Qs = sf;
    float* Ks = sf + OFF_KS;
    float* Vt = sf + OFF_VT;
    float* Ps = sf + OFF_PS;

    const int qb   = blockIdx.x;       // 0..15
    const int h    = blockIdx.y;       // 0..31
    const int kh   = h >> 2;
    const int tid  = threadIdx.x;
    const int wq   = tid >> 5;
    const int lane = tid & 31;
    const int g8   = lane >> 2;
    const int q    = lane & 3;
    const float scale = 0.08838834764831845f;

    const int pp0 = (q < 2) ? 4 * q : 4 * q - 7;
    const int pp1 = (q < 2) ? 4 * q + 2 : 4 * q - 5;

    // Load Q tile (128x128): scaled, tf32, K-permuted
    for (int i = tid; i < 128 * 16; i += 256) {
        int r  = i >> 4;
        int c8 = (i & 15) << 3;
        const float* src = &qkv[(size_t)(qb * 128 + r) * QKVN + h * HD + c8];
        float4 v0 = *(const float4*)src;
        float4 v1 = *(const float4*)(src + 4);
        float y0 = tf32r(v0.x * scale), y1 = tf32r(v0.y * scale);
        float y2 = tf32r(v0.z * scale), y3 = tf32r(v0.w * scale);
        float y4 = tf32r(v1.x * scale), y5 = tf32r(v1.y * scale);
        float y6 = tf32r(v1.z * scale), y7 = tf32r(v1.w * scale);
        float* dst = &Qs[r * FPQ + c8];
        *(float4*)dst       = make_float4(y0, y4, y1, y5);
        *(float4*)(dst + 4) = make_float4(y2, y6, y3, y7);
    }

    float o[16][4];
#pragma unroll
    for (int nt = 0; nt < 16; nt++)
#pragma unroll
        for (int c = 0; c < 4; c++) o[nt][c] = 0.f;
    float m0 = -1e30f, m1 = -1e30f, l0 = 0.f, l1 = 0.f;

    const int row0g = qb * 128 + wq * 16 + g8;   // global q row for c0/c1
    const int row1g = row0g + 8;
    const int jmax  = 2 * qb + 1;

    for (int jt = 0; jt <= jmax; jt++) {
        __syncthreads();
        // K tile (64x128): tf32 + K-permuted
        for (int i = tid; i < 64 * 16; i += 256) {
            int r  = i >> 4;
            int c8 = (i & 15) << 3;
            const float* src = &qkv[(size_t)(jt * 64 + r) * QKVN + NQ * HD + kh * HD + c8];
            float4 v0 = *(const float4*)src;
            float4 v1 = *(const float4*)(src + 4);
            float y0 = tf32r(v0.x), y1 = tf32r(v0.y), y2 = tf32r(v0.z), y3 = tf32r(v0.w);
            float y4 = tf32r(v1.x), y5 = tf32r(v1.y), y6 = tf32r(v1.z), y7 = tf32r(v1.w);
            float* dst = &Ks[r * FPQ + c8];
            *(float4*)dst       = make_float4(y0, y4, y1, y5);
            *(float4*)(dst + 4) = make_float4(y2, y6, y3, y7);
        }
        // V tile transposed: Vt[hd][perm(key)]
        for (int i = tid; i < 64 * 32; i += 256) {
            int r  = i >> 5;                 // key
            int c4 = (i & 31) << 2;          // hd base
            const float* src = &qkv[(size_t)(jt * 64 + r) * QKVN + (NQ + NKV) * HD + kh * HD + c4];
            float4 v = *(const float4*)src;
            int x = r & 7;
            int pr = (r & ~7) | ((x < 4) ? 2 * x : 2 * x - 7);
            Vt[(c4 + 0) * FPV + pr] = tf32r(v.x);
            Vt[(c4 + 1) * FPV + pr] = tf32r(v.y);
            Vt[(c4 + 2) * FPV + pr] = tf32r(v.z);
            Vt[(c4 + 3) * FPV + pr] = tf32r(v.w);
        }
        __syncthreads();

        // S = Q K^T : warp rows [wq*16, wq*16+16), cols [0,64)
        float sacc[8][4];
#pragma unroll
        for (int nt = 0; nt < 8; nt++)
#pragma unroll
            for (int c = 0; c < 4; c++) sacc[nt][c] = 0.f;

#pragma unroll
        for (int ks = 0; ks < 16; ks++) {
            int fo = ks * 8 + q * 2;
            float2 aL = *(const float2*)&Qs[(wq * 16 + g8) * FPQ + fo];
            float2 aH = *(const float2*)&Qs[(wq * 16 + g8 + 8) * FPQ + fo];
            uint32_t a0 = __float_as_uint(aL.x), a1 = __float_as_uint(aH.x);
            uint32_t a2 = __float_as_uint(aL.y), a3 = __float_as_uint(aH.y);
#pragma unroll
            for (int nt = 0; nt < 8; nt++) {
                float2 b = *(const float2*)&Ks[(nt * 8 + g8) * FPQ + fo];
                mma1688(sacc[nt][0], sacc[nt][1], sacc[nt][2], sacc[nt][3],
                        a0, a1, a2, a3, __float_as_uint(b.x), __float_as_uint(b.y));
            }
        }

        // causal mask (only needed near the diagonal)
        if (jt >= 2 * qb) {
#pragma unroll
            for (int nt = 0; nt < 8; nt++) {
                int kc = jt * 64 + nt * 8 + 2 * q;
                if (kc > row0g)     sacc[nt][0] = -1e30f;
                if (kc + 1 > row0g) sacc[nt][1] = -1e30f;
                if (kc > row1g)     sacc[nt][2] = -1e30f;
                if (kc + 1 > row1g) sacc[nt][3] = -1e30f;
            }
        }

        // online softmax (rows warp-local; q-group reductions via shfl)
        float rmax0 = -1e30f, rmax1 = -1e30f;
#pragma unroll
        for (int nt = 0; nt < 8; nt++) {
            rmax0 = fmaxf(rmax0, fmaxf(sacc[nt][0], sacc[nt][1]));
            rmax1 = fmaxf(rmax1, fmaxf(sacc[nt][2], sacc[nt][3]));
        }
        rmax0 = fmaxf(rmax0, __shfl_xor_sync(0xffffffffu, rmax0, 1));
        rmax0 = fmaxf(rmax0, __shfl_xor_sync(0xffffffffu, rmax0, 2));
        rmax1 = fmaxf(rmax1, __shfl_xor_sync(0xffffffffu, rmax1, 1));
        rmax1 = fmaxf(rmax1, __shfl_xor_sync(0xffffffffu, rmax1, 2));

        float nm0 = fmaxf(m0, rmax0), nm1 = fmaxf(m1, rmax1);
        float al0 = __expf(m0 - nm0), al1 = __expf(m1 - nm1);
        m0 = nm0; m1 = nm1;

        float sum0 = 0.f, sum1 = 0.f;
        float* ps0 = &Ps[(wq * 16 + g8) * FPP];
        float* ps1 = &Ps[(wq * 16 + g8 + 8) * FPP];
#pragma unroll
        for (int nt = 0; nt < 8; nt++) {
            float p00 = __expf(sacc[nt][0] - nm0);
            float p01 = __expf(sacc[nt][1] - nm0);
            float p10 = __expf(sacc[nt][2] - nm1);
            float p11 = __expf(sacc[nt][3] - nm1);
            sum0 += p00 + p01;
            sum1 += p10 + p11;
            ps0[nt * 8 + pp0] = tf32r(p00);
            ps0[nt * 8 + pp1] = tf32r(p01);
            ps1[nt * 8 + pp0] = tf32r(p10);
            ps1[nt * 8 + pp1] = tf32r(p11);
        }
        sum0 += __shfl_xor_sync(0xffffffffu, sum0, 1);
        sum0 += __shfl_xor_sync(0xffffffffu, sum0, 2);
        sum1 += __shfl_xor_sync(0xffffffffu, sum1, 1);
        sum1 += __shfl_xor_sync(0xffffffffu, sum1, 2);
        l0 = l0 * al0 + sum0;
        l1 = l1 * al1 + sum1;

#pragma unroll
        for (int nt = 0; nt < 16; nt++) {
            o[nt][0] *= al0; o[nt][1] *= al0;
            o[nt][2] *= al1; o[nt][3] *= al1;
        }

        // O += P V  (Ps rows warp-local; Vt shared but written before sync)
        __syncwarp();
#pragma unroll
        for (int ks = 0; ks < 8; ks++) {
            int fo = ks * 8 + q * 2;
            float2 aL = *(const float2*)&Ps[(wq * 16 + g8) * FPP + fo];
            float2 aH = *(const float2*)&Ps[(wq * 16 + g8 + 8) * FPP + fo];
            uint32_t a0 = __float_as_uint(aL.x), a1 = __float_as_uint(aH.x);
            uint32_t a2 = __float_as_uint(aL.y), a3 = __float_as_uint(aH.y);
#pragma unroll
            for (int nt = 0; nt < 16; nt++) {
                float2 b = *(const float2*)&Vt[(nt * 8 + g8) * FPV + fo];
                mma1688(o[nt][0], o[nt][1], o[nt][2], o[nt][3],
                        a0, a1, a2, a3, __float_as_uint(b.x), __float_as_uint(b.y));
            }
        }
    }

    // normalize, tf32-round, permuted scatter-store
    float invl0 = 1.f / l0, invl1 = 1.f / l1;
    float* a0p = &attn[(size_t)row0g * H + h * HD];
    float* a1p = &attn[(size_t)row1g * H + h * HD];
#pragma unroll
    for (int nt = 0; nt < 16; nt++) {
        a0p[nt * 8 + pp0] = tf32r(o[nt][0] * invl0);
        a0p[nt * 8 + pp1] = tf32r(o[nt][1] * invl0);
        a1p[nt * 8 + pp0] = tf32r(o[nt][2] * invl1);
        a1p[nt * 8 + pp1] = tf32r(o[nt][3] * invl1);
    }
}

// ---------------------------------------------------------------------------
// Launch
// ---------------------------------------------------------------------------
template <typename T>
static float* sym_addr(T& symbol) {
    void* p = nullptr;
    cudaGetSymbolAddress(&p, symbol);
    return (float*)p;
}

extern "C" void kernel_launch(void* const* d_in, const int* in_sizes, int n_in,
                              void* d_out, int out_size) {
    const int*   positions = (const int*)d_in[0];
    const float* hidden    = (const float*)d_in[1];
    const float* w_qkv     = (const float*)d_in[2];
    const float* w_o       = (const float*)d_in[3];
    const float* w_gu      = (const float*)d_in[4];
    const float* w_down    = (const float*)d_in[5];
    const float* ln1       = (const float*)d_in[6];
    const float* ln2       = (const float*)d_in[7];
    float*       out       = (float*)d_out;

    float* xn     = sym_addr(g_xn);
    float* qkv    = sym_addr(g_qkv);
    float* attn   = sym_addr(g_attn);
    float* xn2    = sym_addr(g_xn2);
    float* hh     = sym_addr(g_hh);
    float* wqkvT  = sym_addr(g_wqkvT);
    float* woT    = sym_addr(g_woT);
    float* wguT   = sym_addr(g_wguT);
    float* wdownT = sym_addr(g_wdownT);

    float* resid = (out_size >= 2 * SQ * H) ? out + (size_t)SQ * H : sym_addr(g_res);

    cudaFuncSetAttribute(flash2_kernel, cudaFuncAttributeMaxDynamicSharedMemorySize, FA2_SMEM);
    cudaFuncSetAttribute(gemm_tf32_kernel<0>, cudaFuncAttributeMaxDynamicSharedMemorySize, GEMM_SMEM);
    cudaFuncSetAttribute(gemm_tf32_kernel<1>, cudaFuncAttributeMaxDynamicSharedMemorySize, GEMM_SMEM);
    cudaFuncSetAttribute(gemm_gateup_silu_kernel, cudaFuncAttributeMaxDynamicSharedMemorySize, FGU_SMEM);

    // 0. weight transposes (tf32 + K-permuted)
    transpose_kernel<<<dim3(QKVN / 32, H / 32),  dim3(32, 8)>>>(w_qkv,  wqkvT,  H,  QKVN);
    transpose_kernel<<<dim3(H / 32,    H / 32),  dim3(32, 8)>>>(w_o,    woT,    H,  H);
    transpose_kernel<<<dim3(GUN / 32,  H / 32),  dim3(32, 8)>>>(w_gu,   wguT,   H,  GUN);
    transpose_kernel<<<dim3(H / 32,   II / 32),  dim3(32, 8)>>>(w_down, wdownT, II, H);

    // 1. rmsnorm1 (permuted)
    rmsnorm_perm_kernel<<<SQ, 256>>>(hidden, ln1, xn);
    // 2. qkv = xn @ w_qkv
    gemm_tf32_kernel<0><<<dim3(QKVN / 128, SQ / 128), 256, GEMM_SMEM>>>(SQ, QKVN, H, xn, wqkvT, qkv, nullptr);
    // 3. rope
    rope_kernel<<<dim3(SQ, NQ + NKV), 64>>>(positions, qkv);
    // 4. tensor-core flash attention (permuted output)
    flash2_kernel<<<dim3(SQ / 128, NQ), 256, FA2_SMEM>>>(qkv, attn);
    // 5. residual = attn @ w_o + hidden
    gemm_tf32_kernel<1><<<dim3(H / 128, SQ / 128), 256, GEMM_SMEM>>>(SQ, H, H, attn, woT, resid, hidden);
    // 6. rmsnorm2 (permuted)
    rmsnorm_perm_kernel<<<SQ, 256>>>(resid, ln2, xn2);
    // 7+8. hh = silu(xn2 @ wg) * (xn2 @ wu)  (fused, permuted output)
    gemm_gateup_silu_kernel<<<dim3(II / 128, SQ / 128), 256, FGU_SMEM>>>(SQ, H, xn2, wguT, hh);
    // 9. out = hh @ w_down
    gemm_tf32_kernel<0><<<dim3(H / 128, SQ / 128), 256, GEMM_SMEM>>>(SQ, H, II, hh, wdownT, out, nullptr);
}

// round 5
// speedup vs baseline: 6.5286x; 1.6439x over previous
#include <cuda_runtime.h>
#include <cuda_fp16.h>
#include <cstdint>
#include <math.h>

// Problem constants
#define SQ   2048
#define H    4096
#define NQ   32
#define NKV  8
#define HD   128
#define II   14336
#define QKVN (NQ*HD + 2*NKV*HD)   // 6144
#define GUN  (2*II)               // 28672

// ---------------------------------------------------------------------------
// Scratch (device globals; no allocation anywhere)
// ---------------------------------------------------------------------------
__device__ __half g_xn   [SQ * H];                 // rmsnorm1 out (half, K-perm)
__device__ float  g_qkv  [SQ * QKVN];              // qkv (fp32; rope in place)
__device__ __half g_attn [SQ * H];                 // attention out (half, K-perm)
__device__ __half g_xn2  [SQ * H];                 // rmsnorm2 out (half, K-perm)
__device__ __half g_hh   [(size_t)SQ * II];        // silu(g)*u (half, K-perm)
__device__ float  g_res  [SQ * H];                 // residual fallback
__device__ __half g_wqkvT [(size_t)QKVN * H];
__device__ __half g_woT   [(size_t)H * H];
__device__ __half g_wguT  [(size_t)GUN * H];
__device__ __half g_wdownT[(size_t)H * II];

// ---------------------------------------------------------------------------
// Helpers
// ---------------------------------------------------------------------------
__device__ __forceinline__ void cp16(void* dst_smem, const void* src) {
    uint32_t d = (uint32_t)__cvta_generic_to_shared(dst_smem);
    asm volatile("cp.async.cg.shared.global [%0], [%1], 16;" :: "r"(d), "l"(src));
}
__device__ __forceinline__ void cp_commit() {
    asm volatile("cp.async.commit_group;" ::: "memory");
}
template <int N>
__device__ __forceinline__ void cp_wait() {
    asm volatile("cp.async.wait_group %0;" :: "n"(N) : "memory");
}
// f16 mma: D(16x8,f32) += A(16x16,f16) x B(16x8,f16)
__device__ __forceinline__ void mma16816(float& c0, float& c1, float& c2, float& c3,
                                         uint32_t a0, uint32_t a1, uint32_t a2, uint32_t a3,
                                         uint32_t b0, uint32_t b1) {
    asm volatile(
        "mma.sync.aligned.m16n8k16.row.col.f32.f16.f16.f32 "
        "{%0,%1,%2,%3},{%4,%5,%6,%7},{%8,%9},{%0,%1,%2,%3};"
        : "+f"(c0), "+f"(c1), "+f"(c2), "+f"(c3)
        : "r"(a0), "r"(a1), "r"(a2), "r"(a3), "r"(b0), "r"(b1));
}
// Store one logical 16-half block (x[0..15]) as K-permuted half2 slots.
// perm(g) = (g<4) ? 2g : 2g-7  on half2 granules.
__device__ __forceinline__ void store_block_h2(half2* dst, const float* x) {
#pragma unroll
    for (int g = 0; g < 8; g++) {
        int pg = (g < 4) ? 2 * g : 2 * g - 7;
        dst[pg] = __floats2half2_rn(x[2 * g], x[2 * g + 1]);
    }
}

// ---------------------------------------------------------------------------
// fp16 mma GEMM: C[M,N](f32) = A[M,K](h,perm) @ Bt[N,K](h,perm)^T (+resid f32)
// 128x128x64 tiles, 4-stage cp.async pipeline, 8 warps (2x4 of 64x32).
// Row = 64 data halfs + pad -> 160B stride (==8 words mod 32: conflict-free).
// ---------------------------------------------------------------------------
#define STAGES 4
#define ROWB 160
#define STAGE_A (128 * ROWB)               // 20480 B
#define STAGE_BYTES (2 * STAGE_A)
#define GEMM_SMEM (STAGES * STAGE_BYTES)   // 163840 B

template <int ADD_RESID>
__global__ void __launch_bounds__(256, 1)
gemm_f16_kernel(int M, int N, int K,
                const __half* __restrict__ A,
                const __half* __restrict__ Bt,
                float* __restrict__ C,
                const float* __restrict__ R) {
    extern __shared__ char sm[];

    const int tid  = threadIdx.x;
    const int wid  = tid >> 5;
    const int lane = tid & 31;
    const int wm   = wid >> 2;
    const int wn   = wid & 3;
    const int q    = lane & 3;
    const int g8   = lane >> 2;
    const int m0   = blockIdx.y * 128;
    const int n0   = blockIdx.x * 128;
    const int KT   = K >> 6;

    auto load_stage = [&](int slot, int kt) {
        char* aS = sm + slot * STAGE_BYTES;
        char* bS = aS + STAGE_A;
        const __half* Ag = A  + (size_t)m0 * K + (size_t)kt * 64;
        const __half* Bg = Bt + (size_t)n0 * K + (size_t)kt * 64;
#pragma unroll
        for (int j = 0; j < 4; j++) {
            int idx = tid + j * 256;
            int r = idx >> 3;
            int c = idx & 7;
            cp16(aS + r * ROWB + c * 16, Ag + (size_t)r * K + c * 8);
            cp16(bS + r * ROWB + c * 16, Bg + (size_t)r * K + c * 8);
        }
    };

#pragma unroll
    for (int s = 0; s < STAGES - 1; s++) {
        load_stage(s, s);
        cp_commit();
    }

    float acc[4][4][4];
#pragma unroll
    for (int mt = 0; mt < 4; mt++)
#pragma unroll
        for (int nt = 0; nt < 4; nt++)
#pragma unroll
            for (int c = 0; c < 4; c++) acc[mt][nt][c] = 0.f;

    for (int kt = 0; kt < KT; kt++) {
        cp_wait<STAGES - 2>();
        __syncthreads();

        int nk = kt + STAGES - 1;
        if (nk < KT) load_stage(nk % STAGES, nk);
        cp_commit();

        char* aS = sm + (kt % STAGES) * STAGE_BYTES;
        char* bS = aS + STAGE_A;

#pragma unroll
        for (int ks = 0; ks < 4; ks++) {
            int fo = ks * 32 + q * 8;      // one 16-half k-step = 32B
            uint2 bf[4];
#pragma unroll
            for (int nt = 0; nt < 4; nt++)
                bf[nt] = *(const uint2*)(bS + (wn * 32 + nt * 8 + g8) * ROWB + fo);
#pragma unroll
            for (int mt = 0; mt < 4; mt++) {
                int row = wm * 64 + mt * 16 + g8;
                uint2 aL = *(const uint2*)(aS + row * ROWB + fo);
                uint2 aH = *(const uint2*)(aS + (row + 8) * ROWB + fo);
#pragma unroll
                for (int nt = 0; nt < 4; nt++)
                    mma16816(acc[mt][nt][0], acc[mt][nt][1], acc[mt][nt][2], acc[mt][nt][3],
                             aL.x, aH.x, aL.y, aH.y, bf[nt].x, bf[nt].y);
            }
        }
    }

#pragma unroll
    for (int mt = 0; mt < 4; mt++) {
        int r0 = m0 + wm * 64 + mt * 16 + g8;
#pragma unroll
        for (int nt = 0; nt < 4; nt++) {
            int cc = n0 + wn * 32 + nt * 8 + 2 * q;
            float2 v0 = make_float2(acc[mt][nt][0], acc[mt][nt][1]);
            float2 v1 = make_float2(acc[mt][nt][2], acc[mt][nt][3]);
            if (ADD_RESID) {
                float2 r = *(const float2*)&R[(size_t)r0 * N + cc];
                v0.x += r.x; v0.y += r.y;
                r = *(const float2*)&R[(size_t)(r0 + 8) * N + cc];
                v1.x += r.x; v1.y += r.y;
            }
            *(float2*)&C[(size_t)r0 * N + cc]       = v0;
            *(float2*)&C[(size_t)(r0 + 8) * N + cc] = v1;
        }
    }
}

// ---------------------------------------------------------------------------
// Fused gate/up GEMM + SiLU: hh = halfperm(silu(A@Wg) * (A@Wu)); 3 stages.
// ---------------------------------------------------------------------------
#define FSTAGES 3
#define FSTAGE_BYTES (3 * STAGE_A)
#define FGU_SMEM (FSTAGES * FSTAGE_BYTES)   // 184320 B

__global__ void __launch_bounds__(256, 1)
gemm_gateup_silu_kernel(int M, int K,
                        const __half* __restrict__ A,
                        const __half* __restrict__ Bt,   // [GUN][K]
                        __half* __restrict__ HHout) {
    extern __shared__ char sm[];

    const int tid  = threadIdx.x;
    const int wid  = tid >> 5;
    const int lane = tid & 31;
    const int wm   = wid >> 2;
    const int wn   = wid & 3;
    const int q    = lane & 3;
    const int g8   = lane >> 2;
    const int m0   = blockIdx.y * 128;
    const int n0   = blockIdx.x * 128;
    const int KT   = K >> 6;

    const __half* BG = Bt + (size_t)n0 * K;
    const __half* BU = Bt + (size_t)(II + n0) * K;

    auto load_stage = [&](int slot, int kt) {
        char* aS = sm + slot * FSTAGE_BYTES;
        char* gS = aS + STAGE_A;
        char* uS = gS + STAGE_A;
        const __half* Ag = A + (size_t)m0 * K + (size_t)kt * 64;
        const __half* Gg = BG + (size_t)kt * 64;
        const __half* Ug = BU + (size_t)kt * 64;
#pragma unroll
        for (int j = 0; j < 4; j++) {
            int idx = tid + j * 256;
            int r = idx >> 3;
            int c = idx & 7;
            cp16(aS + r * ROWB + c * 16, Ag + (size_t)r * K + c * 8);
            cp16(gS + r * ROWB + c * 16, Gg + (size_t)r * K + c * 8);
            cp16(uS + r * ROWB + c * 16, Ug + (size_t)r * K + c * 8);
        }
    };

#pragma unroll
    for (int s = 0; s < FSTAGES - 1; s++) {
        load_stage(s, s);
        cp_commit();
    }

    float accG[4][4][4], accU[4][4][4];
#pragma unroll
    for (int mt = 0; mt < 4; mt++)
#pragma unroll
        for (int nt = 0; nt < 4; nt++)
#pragma unroll
            for (int c = 0; c < 4; c++) { accG[mt][nt][c] = 0.f; accU[mt][nt][c] = 0.f; }

    for (int kt = 0; kt < KT; kt++) {
        cp_wait<FSTAGES - 2>();
        __syncthreads();

        int nk = kt + FSTAGES - 1;
        if (nk < KT) load_stage(nk % FSTAGES, nk);
        cp_commit();

        char* aS = sm + (kt % FSTAGES) * FSTAGE_BYTES;
        char* gS = aS + STAGE_A;
        char* uS = gS + STAGE_A;

#pragma unroll
        for (int ks = 0; ks < 4; ks++) {
            int fo = ks * 32 + q * 8;
            uint2 bg[4], bu[4];
#pragma unroll
            for (int nt = 0; nt < 4; nt++) {
                int roff = (wn * 32 + nt * 8 + g8) * ROWB + fo;
                bg[nt] = *(const uint2*)(gS + roff);
                bu[nt] = *(const uint2*)(uS + roff);
            }
#pragma unroll
            for (int mt = 0; mt < 4; mt++) {
                int row = wm * 64 + mt * 16 + g8;
                uint2 aL = *(const uint2*)(aS + row * ROWB + fo);
                uint2 aH = *(const uint2*)(aS + (row + 8) * ROWB + fo);
#pragma unroll
                for (int nt = 0; nt < 4; nt++) {
                    mma16816(accG[mt][nt][0], accG[mt][nt][1], accG[mt][nt][2], accG[mt][nt][3],
                             aL.x, aH.x, aL.y, aH.y, bg[nt].x, bg[nt].y);
                    mma16816(accU[mt][nt][0], accU[mt][nt][1], accU[mt][nt][2], accU[mt][nt][3],
                             aL.x, aH.x, aL.y, aH.y, bu[nt].x, bu[nt].y);
                }
            }
        }
    }

    // epilogue: silu(g)*u -> half2 into K-permuted slot (slot = 2q + (nt&1))
    const int slotq = 2 * q;
#pragma unroll
    for (int mt = 0; mt < 4; mt++) {
        size_t r0 = (size_t)(m0 + wm * 64 + mt * 16 + g8);
        size_t r1 = r0 + 8;
#pragma unroll
        for (int nt = 0; nt < 4; nt++) {
            int gb = n0 + wn * 32 + nt * 8;
            size_t blk2 = (size_t)((gb & ~15) >> 1);   // half2 index of block start
            int slot = slotq + (nt & 1);
            float g0 = accG[mt][nt][0], g1 = accG[mt][nt][1];
            float g2 = accG[mt][nt][2], g3 = accG[mt][nt][3];
            float u0 = accU[mt][nt][0], u1 = accU[mt][nt][1];
            float u2 = accU[mt][nt][2], u3 = accU[mt][nt][3];
            float s0 = g0 / (1.f + __expf(-g0)) * u0;
            float s1 = g1 / (1.f + __expf(-g1)) * u1;
            float s2 = g2 / (1.f + __expf(-g2)) * u2;
            float s3 = g3 / (1.f + __expf(-g3)) * u3;
            ((half2*)HHout)[r0 * (II / 2) + blk2 + slot] = __floats2half2_rn(s0, s1);
            ((half2*)HHout)[r1 * (II / 2) + blk2 + slot] = __floats2half2_rn(s2, s3);
        }
    }
}

// ---------------------------------------------------------------------------
// Weight transpose: out[n][perm16(k)] = half(in[k][n])
// ---------------------------------------------------------------------------
__global__ void transpose_kernel(const float* __restrict__ in, __half* __restrict__ out,
                                 int Kd, int Nd) {
    __shared__ float tile[32][33];
    int k0 = blockIdx.y * 32, n0 = blockIdx.x * 32;
    int tx = threadIdx.x;
#pragma unroll
    for (int i = threadIdx.y; i < 32; i += 8)
        tile[i][tx] = in[(size_t)(k0 + i) * Nd + n0 + tx];
    __syncthreads();
    int blk = tx >> 4, w = tx & 15, g = w >> 1, odd = w & 1;
    int pg = (g < 4) ? 2 * g : 2 * g - 7;
    int pk = blk * 16 + pg * 2 + odd;
#pragma unroll
    for (int i = threadIdx.y; i < 32; i += 8)
        out[(size_t)(n0 + i) * Kd + k0 + pk] = __float2half_rn(tile[tx][i]);
}

// ---------------------------------------------------------------------------
// RMSNorm -> half, K-permuted
// ---------------------------------------------------------------------------
__global__ void rmsnorm_perm_kernel(const float* __restrict__ x,
                                    const float* __restrict__ w,
                                    __half* __restrict__ y) {
    int row = blockIdx.x;
    const float4* xr = (const float4*)(x + (size_t)row * H);
    const float4* wv = (const float4*)w;

    float s = 0.f;
    for (int i = threadIdx.x; i < H / 4; i += 256) {
        float4 v = xr[i];
        s += v.x * v.x + v.y * v.y + v.z * v.z + v.w * v.w;
    }
    __shared__ float red[256];
    red[threadIdx.x] = s;
    __syncthreads();
    for (int off = 128; off; off >>= 1) {
        if (threadIdx.x < off) red[threadIdx.x] += red[threadIdx.x + off];
        __syncthreads();
    }
    float inv = rsqrtf(red[0] / (float)H + 1e-5f);

    // one 16-elem block per thread (H/16 = 256)
    int b = threadIdx.x;
    float xv[16];
    const float* xp = x + (size_t)row * H + b * 16;
    const float* wp = w + b * 16;
#pragma unroll
    for (int j = 0; j < 16; j++) xv[j] = xp[j] * inv * wp[j];
    store_block_h2((half2*)(y + (size_t)row * H + b * 16), xv);
}

// ---------------------------------------------------------------------------
// RoPE (in place on q/k of fp32 qkv)
// ---------------------------------------------------------------------------
__global__ void rope_kernel(const int* __restrict__ pos, float* __restrict__ qkv) {
    int s  = blockIdx.x;
    int hh = blockIdx.y;
    int i  = threadIdx.x;
    int base = (hh < NQ) ? hh * HD : NQ * HD + (hh - NQ) * HD;
    float* p = qkv + (size_t)s * QKVN + base;

    float fpos = (float)pos[s];
    float invf = powf(10000.0f, -(float)i / 64.0f);
    float ang  = fpos * invf;
    float sn, cs;
    sincosf(ang, &sn, &cs);
    float x1 = p[i], x2 = p[i + 64];
    p[i]      = x1 * cs - x2 * sn;
    p[i + 64] = x2 * cs + x1 * sn;
}

// ---------------------------------------------------------------------------
// fp16 tensor-core flash attention (causal, GQA G=4).
// 256 threads, 128 q-rows x head per block, KV tiles of 64.
// Smem (halfs): Qs[128][144], Ks[64][144], Vt[128][80], Ps[128][80].
// All operands K-permuted; output half K-permuted (feeds w_o GEMM).
// ---------------------------------------------------------------------------
#define FQROW 144
#define FVROW 80
#define OFFH_KS (128 * FQROW)                 // 18432
#define OFFH_VT (OFFH_KS + 64 * FQROW)        // 27648
#define OFFH_PS (OFFH_VT + 128 * FVROW)       // 37888
#define FA2_SMEM ((OFFH_PS + 128 * FVROW) * 2)  // 96256 B

__global__ void __launch_bounds__(256, 1)
flash2_kernel(const float* __restrict__ qkv, __half* __restrict__ attn) {
    extern __shared__ __half sh[];
    __half* Qs = sh;
    __half* Ks = sh + OFFH_KS;
    __half* Vt = sh + OFFH_VT;
    __half* Ps = sh + OFFH_PS;

    const int qb   = blockIdx.x;       // 0..15
    const int h    = blockIdx.y;       // 0..31
    const int kh   = h >> 2;
    const int tid  = threadIdx.x;
    const int wq   = tid >> 5;
    const int lane = tid & 31;
    const int g8   = lane >> 2;
    const int q    = lane & 3;
    const float scale = 0.08838834764831845f;

    // Load Q tile (128 rows x 8 blocks of 16): scaled, half, permuted
    for (int i = tid; i < 128 * 8; i += 256) {
        int r = i >> 3;
        int b = i & 7;
        const float* src = &qkv[(size_t)(qb * 128 + r) * QKVN + h * HD + b * 16];
        float xv[16];
#pragma unroll
        for (int j = 0; j < 16; j++) xv[j] = src[j] * scale;
        store_block_h2((half2*)&Qs[r * FQROW + b * 16], xv);
    }

    float o[16][4];
#pragma unroll
    for (int nt = 0; nt < 16; nt++)
#pragma unroll
        for (int c = 0; c < 4; c++) o[nt][c] = 0.f;
    float m0 = -1e30f, m1 = -1e30f, l0 = 0.f, l1 = 0.f;

    const int row0g = qb * 128 + wq * 16 + g8;
    const int row1g = row0g + 8;
    const int jmax  = 2 * qb + 1;

    for (int jt = 0; jt <= jmax; jt++) {
        __syncthreads();
        // K tile (64 rows x 8 blocks), half permuted
        for (int i = tid; i < 64 * 8; i += 256) {
            int r = i >> 3;
            int b = i & 7;
            const float* src = &qkv[(size_t)(jt * 64 + r) * QKVN + NQ * HD + kh * HD + b * 16];
            float xv[16];
#pragma unroll
            for (int j = 0; j < 16; j++) xv[j] = src[j];
            store_block_h2((half2*)&Ks[r * FQROW + b * 16], xv);
        }
        // V tile transposed: Vt[hd][perm(key)]
        for (int i = tid; i < 64 * 32; i += 256) {
            int r  = i >> 5;                 // key
            int c4 = (i & 31) << 2;          // hd base
            const float* src = &qkv[(size_t)(jt * 64 + r) * QKVN + (NQ + NKV) * HD + kh * HD + c4];
            float4 v = *(const float4*)src;
            int blk = r >> 4, w = r & 15, g = w >> 1, odd = w & 1;
            int pg = (g < 4) ? 2 * g : 2 * g - 7;
            int pr = blk * 16 + pg * 2 + odd;
            Vt[(c4 + 0) * FVROW + pr] = __float2half_rn(v.x);
            Vt[(c4 + 1) * FVROW + pr] = __float2half_rn(v.y);
            Vt[(c4 + 2) * FVROW + pr] = __float2half_rn(v.z);
            Vt[(c4 + 3) * FVROW + pr] = __float2half_rn(v.w);
        }
        __syncthreads();

        // S = Q K^T : warp rows [wq*16, +16), cols [0,64)
        float sacc[8][4];
#pragma unroll
        for (int nt = 0; nt < 8; nt++)
#pragma unroll
            for (int c = 0; c < 4; c++) sacc[nt][c] = 0.f;

#pragma unroll
        for (int ks = 0; ks < 8; ks++) {
            int fo = ks * 32 + q * 8;   // bytes
            uint2 aL = *(const uint2*)((const char*)&Qs[(wq * 16 + g8) * FQROW] + fo);
            uint2 aH = *(const uint2*)((const char*)&Qs[(wq * 16 + g8 + 8) * FQROW] + fo);
#pragma unroll
            for (int nt = 0; nt < 8; nt++) {
                uint2 b = *(const uint2*)((const char*)&Ks[(nt * 8 + g8) * FQROW] + fo);
                mma16816(sacc[nt][0], sacc[nt][1], sacc[nt][2], sacc[nt][3],
                         aL.x, aH.x, aL.y, aH.y, b.x, b.y);
            }
        }

        // causal mask near the diagonal
        if (jt >= 2 * qb) {
#pragma unroll
            for (int nt = 0; nt < 8; nt++) {
                int kc = jt * 64 + nt * 8 + 2 * q;
                if (kc > row0g)     sacc[nt][0] = -1e30f;
                if (kc + 1 > row0g) sacc[nt][1] = -1e30f;
                if (kc > row1g)     sacc[nt][2] = -1e30f;
                if (kc + 1 > row1g) sacc[nt][3] = -1e30f;
            }
        }

        // online softmax
        float rmax0 = -1e30f, rmax1 = -1e30f;
#pragma unroll
        for (int nt = 0; nt < 8; nt++) {
            rmax0 = fmaxf(rmax0, fmaxf(sacc[nt][0], sacc[nt][1]));
            rmax1 = fmaxf(rmax1, fmaxf(sacc[nt][2], sacc[nt][3]));
        }
        rmax0 = fmaxf(rmax0, __shfl_xor_sync(0xffffffffu, rmax0, 1));
        rmax0 = fmaxf(rmax0, __shfl_xor_sync(0xffffffffu, rmax0, 2));
        rmax1 = fmaxf(rmax1, __shfl_xor_sync(0xffffffffu, rmax1, 1));
        rmax1 = fmaxf(rmax1, __shfl_xor_sync(0xffffffffu, rmax1, 2));

        float nm0 = fmaxf(m0, rmax0), nm1 = fmaxf(m1, rmax1);
        float al0 = __expf(m0 - nm0), al1 = __expf(m1 - nm1);
        m0 = nm0; m1 = nm1;

        float sum0 = 0.f, sum1 = 0.f;
        half2* ps0 = (half2*)&Ps[(wq * 16 + g8) * FVROW];
        half2* ps1 = (half2*)&Ps[(wq * 16 + g8 + 8) * FVROW];
#pragma unroll
        for (int nt = 0; nt < 8; nt++) {
            float p00 = __expf(sacc[nt][0] - nm0);
            float p01 = __expf(sacc[nt][1] - nm0);
            float p10 = __expf(sacc[nt][2] - nm1);
            float p11 = __expf(sacc[nt][3] - nm1);
            sum0 += p00 + p01;
            sum1 += p10 + p11;
            int slot = (nt >> 1) * 8 + 2 * q + (nt & 1);
            ps0[slot] = __floats2half2_rn(p00, p01);
            ps1[slot] = __floats2half2_rn(p10, p11);
        }
        sum0 += __shfl_xor_sync(0xffffffffu, sum0, 1);
        sum0 += __shfl_xor_sync(0xffffffffu, sum0, 2);
        sum1 += __shfl_xor_sync(0xffffffffu, sum1, 1);
        sum1 += __shfl_xor_sync(0xffffffffu, sum1, 2);
        l0 = l0 * al0 + sum0;
        l1 = l1 * al1 + sum1;

#pragma unroll
        for (int nt = 0; nt < 16; nt++) {
            o[nt][0] *= al0; o[nt][1] *= al0;
            o[nt][2] *= al1; o[nt][3] *= al1;
        }

        // O += P V
        __syncwarp();
#pragma unroll
        for (int ks = 0; ks < 4; ks++) {
            int fo = ks * 32 + q * 8;
            uint2 aL = *(const uint2*)((const char*)&Ps[(wq * 16 + g8) * FVROW] + fo);
            uint2 aH = *(const uint2*)((const char*)&Ps[(wq * 16 + g8 + 8) * FVROW] + fo);
#pragma unroll
            for (int nt = 0; nt < 16; nt++) {
                uint2 b = *(const uint2*)((const char*)&Vt[(nt * 8 + g8) * FVROW] + fo);
                mma16816(o[nt][0], o[nt][1], o[nt][2], o[nt][3],
                         aL.x, aH.x, aL.y, aH.y, b.x, b.y);
            }
        }
    }

    // normalize + permuted half2 store
    float invl0 = 1.f / l0, invl1 = 1.f / l1;
    half2* a0p = (half2*)(attn + (size_t)row0g * H + h * HD);
    half2* a1p = (half2*)(attn + (size_t)row1g * H + h * HD);
#pragma unroll
    for (int nt = 0; nt < 16; nt++) {
        int slot = (nt >> 1) * 8 + 2 * q + (nt & 1);
        a0p[slot] = __floats2half2_rn(o[nt][0] * invl0, o[nt][1] * invl0);
        a1p[slot] = __floats2half2_rn(o[nt][2] * invl1, o[nt][3] * invl1);
    }
}

// ---------------------------------------------------------------------------
// Launch
// ---------------------------------------------------------------------------
template <typename P, typename T>
static P sym_addr(T& symbol) {
    void* p = nullptr;
    cudaGetSymbolAddress(&p, symbol);
    return (P)p;
}

extern "C" void kernel_launch(void* const* d_in, const int* in_sizes, int n_in,
                              void* d_out, int out_size) {
    const int*   positions = (const int*)d_in[0];
    const float* hidden    = (const float*)d_in[1];
    const float* w_qkv     = (const float*)d_in[2];
    const float* w_o       = (const float*)d_in[3];
    const float* w_gu      = (const float*)d_in[4];
    const float* w_down    = (const float*)d_in[5];
    const float* ln1       = (const float*)d_in[6];
    const float* ln2       = (const float*)d_in[7];
    float*       out       = (float*)d_out;

    __half* xn     = sym_addr<__half*>(g_xn);
    float*  qkv    = sym_addr<float*>(g_qkv);
    __half* attn   = sym_addr<__half*>(g_attn);
    __half* xn2    = sym_addr<__half*>(g_xn2);
    __half* hh     = sym_addr<__half*>(g_hh);
    __half* wqkvT  = sym_addr<__half*>(g_wqkvT);
    __half* woT    = sym_addr<__half*>(g_woT);
    __half* wguT   = sym_addr<__half*>(g_wguT);
    __half* wdownT = sym_addr<__half*>(g_wdownT);

    float* resid = (out_size >= 2 * SQ * H) ? out + (size_t)SQ * H : sym_addr<float*>(g_res);

    cudaFuncSetAttribute(flash2_kernel, cudaFuncAttributeMaxDynamicSharedMemorySize, FA2_SMEM);
    cudaFuncSetAttribute(gemm_f16_kernel<0>, cudaFuncAttributeMaxDynamicSharedMemorySize, GEMM_SMEM);
    cudaFuncSetAttribute(gemm_f16_kernel<1>, cudaFuncAttributeMaxDynamicSharedMemorySize, GEMM_SMEM);
    cudaFuncSetAttribute(gemm_gateup_silu_kernel, cudaFuncAttributeMaxDynamicSharedMemorySize, FGU_SMEM);

    // 0. weight transposes (half + K-permuted)
    transpose_kernel<<<dim3(QKVN / 32, H / 32),  dim3(32, 8)>>>(w_qkv,  wqkvT,  H,  QKVN);
    transpose_kernel<<<dim3(H / 32,    H / 32),  dim3(32, 8)>>>(w_o,    woT,    H,  H);
    transpose_kernel<<<dim3(GUN / 32,  H / 32),  dim3(32, 8)>>>(w_gu,   wguT,   H,  GUN);
    transpose_kernel<<<dim3(H / 32,   II / 32),  dim3(32, 8)>>>(w_down, wdownT, II, H);

    // 1. rmsnorm1 (half perm)
    rmsnorm_perm_kernel<<<SQ, 256>>>(hidden, ln1, xn);
    // 2. qkv = xn @ w_qkv (fp32 out)
    gemm_f16_kernel<0><<<dim3(QKVN / 128, SQ / 128), 256, GEMM_SMEM>>>(SQ, QKVN, H, xn, wqkvT, qkv, nullptr);
    // 3. rope
    rope_kernel<<<dim3(SQ, NQ + NKV), 64>>>(positions, qkv);
    // 4. fp16 flash attention (half-perm out)
    flash2_kernel<<<dim3(SQ / 128, NQ), 256, FA2_SMEM>>>(qkv, attn);
    // 5. residual = attn @ w_o + hidden (fp32 out)
    gemm_f16_kernel<1><<<dim3(H / 128, SQ / 128), 256, GEMM_SMEM>>>(SQ, H, H, attn, woT, resid, hidden);
    // 6. rmsnorm2 (half perm)
    rmsnorm_perm_kernel<<<SQ, 256>>>(resid, ln2, xn2);
    // 7+8. hh = silu(xn2 @ wg) * (xn2 @ wu) (fused, half perm)
    gemm_gateup_silu_kernel<<<dim3(II / 128, SQ / 128), 256, FGU_SMEM>>>(SQ, H, xn2, wguT, hh);
    // 9. out = hh @ w_down (fp32 out)
    gemm_f16_kernel<0><<<dim3(H / 128, SQ / 128), 256, GEMM_SMEM>>>(SQ, H, II, hh, wdownT, out, nullptr);
}